// round 3
// baseline (speedup 1.0000x reference)
#include <cuda_runtime.h>
#include <cstdint>

// Problem constants
#define BSZ 16384
#define HD  512
#define NC  62
#define UU  8
// per-unit slab size in floats: 16384*512 = 1<<23
#define SLAB ((size_t)1 << 23)

// ---------------- scratch (device globals; no allocation allowed) -------------
__device__ float g_bufA[(size_t)UU * BSZ * HD];   // 256 MB: h0, then h1
__device__ float g_bufB[(size_t)UU * BSZ * HD];   // 256 MB: a1
__device__ float g_w2p[UU * HD * 64];             // W2eff padded [8][512][64]
__device__ float g_c1n[64];                       // normalized policy1 [t][f]
__device__ float g_c2g[64];                       // g_j * normalized policy2 [j][f]
__device__ float g_gbias[64];                     // folded output bias (padded)

// ---------------- f32x2 packed-FMA helpers (Blackwell FFMA2) ------------------
__device__ __forceinline__ unsigned long long pack2(float x) {
    unsigned long long r;
    unsigned int xi = __float_as_uint(x);
    asm("mov.b64 %0, {%1, %2};" : "=l"(r) : "r"(xi), "r"(xi));
    return r;
}
__device__ __forceinline__ void fma2(unsigned long long& d,
                                     unsigned long long a,
                                     unsigned long long b) {
    asm("fma.rn.f32x2 %0, %1, %2, %0;" : "+l"(d) : "l"(a), "l"(b));
}
__device__ __forceinline__ float2 unpack2(unsigned long long v) {
    float2 f;
    asm("mov.b64 {%0, %1}, %2;" : "=f"(f.x), "=f"(f.y) : "l"(v));
    return f;
}

// ---------------- prep: tiny policy/bias folding ------------------------------
__global__ void prep_small_kernel(const float* __restrict__ p1,
                                  const float* __restrict__ p2,
                                  const float* __restrict__ pf,
                                  const float* __restrict__ b2) {
    __shared__ float gs[8];
    int t = threadIdx.x;
    if (t == 0) {
        float d = 0.f;
        for (int j = 0; j < 8; j++) d += pf[j];
        float inv = d > 0.f ? 1.f / d : 1.f;
        float acc = 1.f;
        for (int j = 7; j >= 0; --j) { acc *= inv; gs[j] = pf[j] * acc; }  // g_j = pf[j]*inv^(8-j)
    }
    __syncthreads();
    if (t < 8) {
        float r1 = 0.f, r2 = 0.f;
        for (int f = 0; f < 8; f++) { r1 += p1[t * 8 + f]; r2 += p2[t * 8 + f]; }
        float i1 = r1 > 0.f ? 1.f / r1 : 1.f;
        float i2 = r2 > 0.f ? 1.f / r2 : 1.f;
        for (int f = 0; f < 8; f++) {
            g_c1n[t * 8 + f] = p1[t * 8 + f] * i1;
            g_c2g[t * 8 + f] = gs[t] * p2[t * 8 + f] * i2;
        }
    }
    if (t < 62) {
        float s = 0.f;
        for (int j = 0; j < 8; j++) s += gs[j] * b2[j * NC + t];
        g_gbias[t] = s;
    } else if (t < 64) {
        g_gbias[t] = 0.f;
    }
}

// W2eff[f][d][c] = sum_j c2g[j][f] * W2[j][d][c]   (padded to 64 cols)
__global__ void prep_w2eff_kernel(const float* __restrict__ W2) {
    int idx = blockIdx.x * 256 + threadIdx.x;   // 8*512*64 = 262144 total
    int f = idx >> 15;
    int r = idx & 32767;
    int d = r >> 6, c = r & 63;
    float s = 0.f;
    if (c < NC) {
        #pragma unroll
        for (int j = 0; j < 8; j++)
            s = fmaf(g_c2g[j * 8 + f], W2[((size_t)(j * 512) + d) * NC + c], s);
    }
    g_w2p[idx] = s;
}

// ---------------- main 512x512 GEMM with bias+relu (stages A and C) -----------
// C[u] = relu(A[u] @ W[u] + bias[u]); M=16384, N=512, K=512
// BM=128 BN=128 BK=16, 256 threads, 8x8 thread tile, f32x2 inner product.
__global__ __launch_bounds__(256, 2)
void gemm512_kernel(const float* __restrict__ Aext, int useExt,
                    const float* __restrict__ W, const float* __restrict__ bias) {
    const int u  = blockIdx.z;
    const int bm = blockIdx.x * 128;
    const int bn = blockIdx.y * 128;

    const float* Abase = useExt ? Aext : (const float*)g_bufB;
    const size_t astride = useExt ? (size_t)0 : SLAB;
    const float* Ab = Abase + (size_t)u * astride + (size_t)bm * HD;
    const float* Wb = W + ((size_t)u << 18) + bn;               // 512*512 per unit
    float* Ob = g_bufA + ((size_t)u * SLAB) + (size_t)bm * HD + bn;

    __shared__ __align__(16) float As[2][16][132];  // A transposed [k][m], padded
    __shared__ __align__(16) float Bs[2][16][128];

    const int t  = threadIdx.x;
    const int tx = t & 15, ty = t >> 4;
    // global-load mapping
    const int am = t >> 2;            // 0..63 (two row groups: am, am+64)
    const int ak = (t & 3) << 2;      // 0,4,8,12
    const int wk = t >> 5;            // 0..7   (two k groups: wk, wk+8)
    const int wn = (t & 31) << 2;     // 0..124

    unsigned long long acc[8][4];
    #pragma unroll
    for (int i = 0; i < 8; i++)
        #pragma unroll
        for (int j = 0; j < 4; j++) acc[i][j] = 0ULL;

    float4 ra[2], rb[2];

    // prologue: load tile 0
    #pragma unroll
    for (int r = 0; r < 2; r++) {
        ra[r] = *(const float4*)(Ab + (size_t)(am + r * 64) * HD + ak);
        rb[r] = *(const float4*)(Wb + (size_t)(wk + r * 8) * HD + wn);
    }
    #pragma unroll
    for (int r = 0; r < 2; r++) {
        As[0][ak + 0][am + r * 64] = ra[r].x;
        As[0][ak + 1][am + r * 64] = ra[r].y;
        As[0][ak + 2][am + r * 64] = ra[r].z;
        As[0][ak + 3][am + r * 64] = ra[r].w;
        *(float4*)&Bs[0][wk + r * 8][wn] = rb[r];
    }
    __syncthreads();

    #pragma unroll 1
    for (int kt = 0; kt < 32; ++kt) {
        const int s = kt & 1;
        if (kt < 31) {
            const int k0 = (kt + 1) * 16;
            #pragma unroll
            for (int r = 0; r < 2; r++) {
                ra[r] = *(const float4*)(Ab + (size_t)(am + r * 64) * HD + k0 + ak);
                rb[r] = *(const float4*)(Wb + (size_t)(k0 + wk + r * 8) * HD + wn);
            }
        }
        // compute this tile
        #pragma unroll
        for (int k = 0; k < 16; ++k) {
            float4 a0 = *(const float4*)&As[s][k][ty * 8];
            float4 a1 = *(const float4*)&As[s][k][ty * 8 + 4];
            ulonglong2 b01 = *(const ulonglong2*)&Bs[s][k][tx * 8];
            ulonglong2 b23 = *(const ulonglong2*)&Bs[s][k][tx * 8 + 4];
            unsigned long long bp[4] = {b01.x, b01.y, b23.x, b23.y};
            float av[8] = {a0.x, a0.y, a0.z, a0.w, a1.x, a1.y, a1.z, a1.w};
            #pragma unroll
            for (int i = 0; i < 8; i++) {
                unsigned long long ad = pack2(av[i]);
                #pragma unroll
                for (int j = 0; j < 4; j++) fma2(acc[i][j], ad, bp[j]);
            }
        }
        if (kt < 31) {
            const int sn = 1 - s;
            #pragma unroll
            for (int r = 0; r < 2; r++) {
                As[sn][ak + 0][am + r * 64] = ra[r].x;
                As[sn][ak + 1][am + r * 64] = ra[r].y;
                As[sn][ak + 2][am + r * 64] = ra[r].z;
                As[sn][ak + 3][am + r * 64] = ra[r].w;
                *(float4*)&Bs[sn][wk + r * 8][wn] = rb[r];
            }
        }
        __syncthreads();
    }

    // epilogue: bias + relu, vectorized store
    float bv[8];
    const float* bptr = bias + u * HD + bn + tx * 8;
    #pragma unroll
    for (int j = 0; j < 8; j++) bv[j] = bptr[j];
    #pragma unroll
    for (int i = 0; i < 8; i++) {
        float v[8];
        #pragma unroll
        for (int j = 0; j < 4; j++) {
            float2 p = unpack2(acc[i][j]);
            v[2 * j] = p.x; v[2 * j + 1] = p.y;
        }
        #pragma unroll
        for (int j = 0; j < 8; j++) {
            float z = v[j] + bv[j];
            v[j] = z > 0.f ? z : 0.f;
        }
        float4* dst = (float4*)(Ob + (size_t)(ty * 8 + i) * HD + tx * 8);
        dst[0] = make_float4(v[0], v[1], v[2], v[3]);
        dst[1] = make_float4(v[4], v[5], v[6], v[7]);
    }
}

// ---------------- aggregation: a1[t] = sum_f c1n[t,f]*h0[f] (elementwise) ------
__global__ void agg1_kernel() {
    __shared__ float c1s[64];
    int t = threadIdx.x;
    if (t < 64) c1s[t] = g_c1n[t];
    __syncthreads();
    size_t off = ((size_t)blockIdx.x * 256 + t) << 2;   // float offset of float4
    float4 h[8];
    #pragma unroll
    for (int f = 0; f < 8; f++)
        h[f] = *(const float4*)(g_bufA + (size_t)f * SLAB + off);
    #pragma unroll
    for (int u = 0; u < 8; u++) {
        float4 s = make_float4(0.f, 0.f, 0.f, 0.f);
        #pragma unroll
        for (int f = 0; f < 8; f++) {
            float c = c1s[u * 8 + f];
            s.x = fmaf(c, h[f].x, s.x);
            s.y = fmaf(c, h[f].y, s.y);
            s.z = fmaf(c, h[f].z, s.z);
            s.w = fmaf(c, h[f].w, s.w);
        }
        *(float4*)(g_bufB + (size_t)u * SLAB + off) = s;
    }
}

// ---------------- output GEMM: out[b,c] = sum_f h1[f][b,:] @ W2eff[f] + gbias --
// M=16384, N=62(pad 64), K=8*512. BM=64, BN=64, BK=16, 256 threads, 4x4 tile.
__global__ __launch_bounds__(256)
void gemm_out_kernel(float* __restrict__ Out) {
    const int bm = blockIdx.x * 64;
    const int t  = threadIdx.x;
    const int tx = t & 15, ty = t >> 4;
    const int am = t >> 2,  ak  = (t & 3) << 2;
    const int bk = t >> 4,  bn4 = (t & 15) << 2;

    __shared__ __align__(16) float As[2][16][68];
    __shared__ __align__(16) float Bs[2][16][64];

    unsigned long long acc[4][2];
    #pragma unroll
    for (int i = 0; i < 4; i++) { acc[i][0] = 0ULL; acc[i][1] = 0ULL; }

    float4 ra, rb;
    // prologue (f=0, k0=0)
    ra = *(const float4*)(g_bufA + (size_t)(bm + am) * HD + ak);
    rb = *(const float4*)(g_w2p + bk * 64 + bn4);
    As[0][ak + 0][am] = ra.x; As[0][ak + 1][am] = ra.y;
    As[0][ak + 2][am] = ra.z; As[0][ak + 3][am] = ra.w;
    *(float4*)&Bs[0][bk][bn4] = rb;
    __syncthreads();

    #pragma unroll 1
    for (int ft = 0; ft < 256; ++ft) {
        const int s = ft & 1;
        if (ft < 255) {
            const int fn  = (ft + 1) >> 5;
            const int k0n = ((ft + 1) & 31) << 4;
            ra = *(const float4*)(g_bufA + (size_t)fn * SLAB + (size_t)(bm + am) * HD + k0n + ak);
            rb = *(const float4*)(g_w2p + fn * 32768 + (k0n + bk) * 64 + bn4);
        }
        #pragma unroll
        for (int k = 0; k < 16; ++k) {
            float4 a = *(const float4*)&As[s][k][ty * 4];
            ulonglong2 bb = *(const ulonglong2*)&Bs[s][k][tx * 4];
            float av[4] = {a.x, a.y, a.z, a.w};
            #pragma unroll
            for (int i = 0; i < 4; i++) {
                unsigned long long ad = pack2(av[i]);
                fma2(acc[i][0], ad, bb.x);
                fma2(acc[i][1], ad, bb.y);
            }
        }
        if (ft < 255) {
            const int sn = 1 - s;
            As[sn][ak + 0][am] = ra.x; As[sn][ak + 1][am] = ra.y;
            As[sn][ak + 2][am] = ra.z; As[sn][ak + 3][am] = ra.w;
            *(float4*)&Bs[sn][bk][bn4] = rb;
        }
        __syncthreads();
    }

    float gb[4];
    #pragma unroll
    for (int j = 0; j < 4; j++) gb[j] = g_gbias[tx * 4 + j];
    #pragma unroll
    for (int i = 0; i < 4; i++) {
        int m = bm + ty * 4 + i;
        float2 p0 = unpack2(acc[i][0]);
        float2 p1 = unpack2(acc[i][1]);
        float v[4] = {p0.x + gb[0], p0.y + gb[1], p1.x + gb[2], p1.y + gb[3]};
        #pragma unroll
        for (int j = 0; j < 4; j++) {
            int c = tx * 4 + j;
            if (c < NC) Out[(size_t)m * NC + c] = v[j];
        }
    }
}

// ---------------- launch ------------------------------------------------------
extern "C" void kernel_launch(void* const* d_in, const int* in_sizes, int n_in,
                              void* d_out, int out_size) {
    const float* x  = (const float*)d_in[0];
    const float* p1 = (const float*)d_in[1];
    const float* p2 = (const float*)d_in[2];
    const float* pf = (const float*)d_in[3];
    const float* W0 = (const float*)d_in[4];
    const float* b0 = (const float*)d_in[5];
    const float* W1 = (const float*)d_in[6];
    const float* b1 = (const float*)d_in[7];
    const float* W2 = (const float*)d_in[8];
    const float* b2 = (const float*)d_in[9];
    float* out = (float*)d_out;

    // fold policies + output-layer weights
    prep_small_kernel<<<1, 64>>>(p1, p2, pf, b2);
    prep_w2eff_kernel<<<1024, 256>>>(W2);

    // stage A: h0[u] = relu(x @ W0[u] + b0[u]) -> g_bufA
    gemm512_kernel<<<dim3(128, 4, 8), 256>>>(x, 1, W0, b0);

    // aggregation: a1 = c1n-mix(h0) -> g_bufB
    agg1_kernel<<<8192, 256>>>();

    // stage C: h1[u] = relu(a1[u] @ W1[u] + b1[u]) -> g_bufA
    gemm512_kernel<<<dim3(128, 4, 8), 256>>>(nullptr, 0, W1, b1);

    // output: out = sum_f h1[f] @ W2eff[f] + gbias
    gemm_out_kernel<<<256, 256>>>(out);
}

// round 5
// speedup vs baseline: 1.9228x; 1.9228x over previous
#include <cuda_runtime.h>
#include <cuda_bf16.h>
#include <cstdint>

// Problem constants
#define BSZ 16384
#define HD  512
#define NC  62
#define UU  8
#define SLAB ((size_t)1 << 23)   // 16384*512 floats per unit

// ---------------- scratch (device globals; no allocation allowed) -------------
__device__ float g_bufA[(size_t)UU * BSZ * HD];   // 256 MB: h0, then h1
__device__ float g_bufB[(size_t)UU * BSZ * HD];   // 256 MB: a1
__device__ float g_w2p[UU * HD * 64];             // W2eff padded [8][512][64]
__device__ float g_c1n[64];                       // normalized policy1
__device__ float g_c2g[64];                       // g_j * normalized policy2
__device__ float g_gbias[64];                     // folded output bias
// packed split weights per (layer,u,ktile): hi plane [n=512][k=32] bf16, then lo
__device__ unsigned short g_wpk[(size_t)2 * 8 * 16 * 32768];   // 16 MB

// ---------------- f32x2 packed-FMA helpers (SIMT output GEMM) -----------------
__device__ __forceinline__ unsigned long long pack2(float x) {
    unsigned long long r; unsigned int xi = __float_as_uint(x);
    asm("mov.b64 %0, {%1, %2};" : "=l"(r) : "r"(xi), "r"(xi));
    return r;
}
__device__ __forceinline__ void fma2(unsigned long long& d, unsigned long long a,
                                     unsigned long long b) {
    asm("fma.rn.f32x2 %0, %1, %2, %0;" : "+l"(d) : "l"(a), "l"(b));
}
__device__ __forceinline__ float2 unpack2(unsigned long long v) {
    float2 f; asm("mov.b64 {%0, %1}, %2;" : "=f"(f.x), "=f"(f.y) : "l"(v));
    return f;
}

// ---------------- HMMA m16n8k16 bf16 (baseline PTX, sm_80+) -------------------
__device__ __forceinline__ void mma16816(float* c, const uint32_t* a,
                                         uint32_t b0, uint32_t b1) {
    asm volatile(
        "mma.sync.aligned.m16n8k16.row.col.f32.bf16.bf16.f32 "
        "{%0,%1,%2,%3}, {%4,%5,%6,%7}, {%8,%9}, {%0,%1,%2,%3};"
        : "+f"(c[0]), "+f"(c[1]), "+f"(c[2]), "+f"(c[3])
        : "r"(a[0]), "r"(a[1]), "r"(a[2]), "r"(a[3]), "r"(b0), "r"(b1));
}

// ---------------- prep: tiny policy/bias folding ------------------------------
__global__ void prep_small_kernel(const float* __restrict__ p1,
                                  const float* __restrict__ p2,
                                  const float* __restrict__ pf,
                                  const float* __restrict__ b2) {
    __shared__ float gs[8];
    int t = threadIdx.x;
    if (t == 0) {
        float d = 0.f;
        for (int j = 0; j < 8; j++) d += pf[j];
        float inv = d > 0.f ? 1.f / d : 1.f;
        float acc = 1.f;
        for (int j = 7; j >= 0; --j) { acc *= inv; gs[j] = pf[j] * acc; }
    }
    __syncthreads();
    if (t < 8) {
        float r1 = 0.f, r2 = 0.f;
        for (int f = 0; f < 8; f++) { r1 += p1[t * 8 + f]; r2 += p2[t * 8 + f]; }
        float i1 = r1 > 0.f ? 1.f / r1 : 1.f;
        float i2 = r2 > 0.f ? 1.f / r2 : 1.f;
        for (int f = 0; f < 8; f++) {
            g_c1n[t * 8 + f] = p1[t * 8 + f] * i1;
            g_c2g[t * 8 + f] = gs[t] * p2[t * 8 + f] * i2;
        }
    }
    if (t < 62) {
        float s = 0.f;
        for (int j = 0; j < 8; j++) s += gs[j] * b2[j * NC + t];
        g_gbias[t] = s;
    } else if (t < 64) {
        g_gbias[t] = 0.f;
    }
}

__global__ void prep_w2eff_kernel(const float* __restrict__ W2) {
    int idx = blockIdx.x * 256 + threadIdx.x;
    int f = idx >> 15;
    int r = idx & 32767;
    int d = r >> 6, c = r & 63;
    float s = 0.f;
    if (c < NC) {
        #pragma unroll
        for (int j = 0; j < 8; j++)
            s = fmaf(g_c2g[j * 8 + f], W2[((size_t)(j * 512) + d) * NC + c], s);
    }
    g_w2p[idx] = s;
}

// ---------------- weight transpose + bf16 hi/lo split --------------------------
// per (l,u,kt): hi[n*32+k] then lo[n*32+k], n<512, k<32 (k = kt*32 + k_local)
__global__ void conv_w_kernel(const float* __restrict__ W0, const float* __restrict__ W1) {
    int idx = blockIdx.x * 256 + threadIdx.x;   // 131072 total
    int n  = idx & 511;
    int r  = idx >> 9;          // (l*8+u)*16 + kt, < 256
    int kt = r & 15;
    int ug = r >> 4;
    const float* W = (ug >= 8 ? W1 : W0) + ((size_t)(ug & 7) << 18);
    unsigned short hv[32], lv[32];
    #pragma unroll 8
    for (int i = 0; i < 32; i++) {
        float x = W[(size_t)(kt * 32 + i) * 512 + n];
        __nv_bfloat16 h = __float2bfloat16(x);
        float res = x - __bfloat162float(h);
        __nv_bfloat16 l = __float2bfloat16(res);
        hv[i] = __bfloat16_as_ushort(h);
        lv[i] = __bfloat16_as_ushort(l);
    }
    unsigned short* dst = g_wpk + (size_t)r * 32768 + n * 32;
    #pragma unroll
    for (int i = 0; i < 4; i++) {
        *(uint4*)(dst + i * 8)          = *(uint4*)(hv + i * 8);
        *(uint4*)(dst + 16384 + i * 8)  = *(uint4*)(lv + i * 8);
    }
}

// =========== HMMA bf16-split GEMM: C[u] = relu(A[u] @ W[u] + b[u]) ============
// M=16384, N=512, K=512. BM=128, BN=128, BK=32. 256 thr, 8 warps 4x2,
// warp tile 32x64 (2 m-frags x 8 n-frags). SMEM stride 40 bf16 (80 B) rows
// -> fragment LDS is bank-conflict-free. Double buffered via register staging.
#define PLANE 10240                 // 128 rows * 80 B
#define BUFB  (4 * PLANE)           // Ahi, Alo, Bhi, Blo
#define GEMM_SMEM (2 * BUFB)        // 81920

__global__ __launch_bounds__(256, 2)
void gemm_tc_kernel(const float* __restrict__ Aext, int useExt, int layer,
                    const float* __restrict__ bias) {
    extern __shared__ __align__(16) char dsm[];
    __shared__ float sBias[512];

    const int tid = threadIdx.x;
    const int wid = tid >> 5, lane = tid & 31;
    const int g = lane >> 2, t4 = lane & 3;
    const int wm = (wid >> 1) * 32;       // warp m offset (4 warps down M)
    const int wn = (wid & 1) * 64;        // warp n offset (2 warps across N)
    const int u  = blockIdx.z;
    const int bm = blockIdx.x * 128;
    const int bn = blockIdx.y * 128;

    const float* Ab = useExt ? (Aext + (size_t)bm * HD)
                             : ((const float*)g_bufB + (size_t)u * SLAB + (size_t)bm * HD);
    const unsigned short* Wb = g_wpk + (size_t)((layer * 8 + u) * 16) * 32768;
    float* Ob = g_bufA + (size_t)u * SLAB + (size_t)bm * HD + bn;

    ((float2*)sBias)[tid] = ((const float2*)(bias + u * HD))[tid];

    float acc[2][8][4];
    #pragma unroll
    for (int i = 0; i < 2; i++)
        #pragma unroll
        for (int j = 0; j < 8; j++)
            #pragma unroll
            for (int q = 0; q < 4; q++) acc[i][j][q] = 0.f;

    float4 ra[4];
    uint4  rb[4];

    // global-load lane mapping
    const int arow = tid >> 3, ac4 = tid & 7;            // A: 4 float4/thread

    // ---- prologue: tile 0 -> regs -> smem buf 0 ----
    #pragma unroll
    for (int i = 0; i < 4; i++)
        ra[i] = *(const float4*)(Ab + (size_t)(arow + i * 32) * HD + ac4 * 4);
    #pragma unroll
    for (int i = 0; i < 4; i++) {
        int f = i * 256 + tid, pl = f >> 9, fr = f & 511, row = fr >> 2, q = fr & 3;
        rb[i] = *(const uint4*)(Wb + (size_t)pl * 16384 + (size_t)(bn + row) * 32 + q * 8);
    }
    {
        char* aHi = dsm;            char* aLo = dsm + PLANE;
        char* bHi = dsm + 2 * PLANE; char* bLo = dsm + 3 * PLANE;
        #pragma unroll
        for (int i = 0; i < 4; i++) {
            float4 v = ra[i];
            __nv_bfloat16 h0 = __float2bfloat16(v.x), h1 = __float2bfloat16(v.y),
                          h2 = __float2bfloat16(v.z), h3 = __float2bfloat16(v.w);
            __nv_bfloat16 l0 = __float2bfloat16(v.x - __bfloat162float(h0));
            __nv_bfloat16 l1 = __float2bfloat16(v.y - __bfloat162float(h1));
            __nv_bfloat16 l2 = __float2bfloat16(v.z - __bfloat162float(h2));
            __nv_bfloat16 l3 = __float2bfloat16(v.w - __bfloat162float(h3));
            uint32_t off = (arow + i * 32) * 80 + ac4 * 8;
            *(uint2*)(aHi + off) = make_uint2(
                (uint32_t)__bfloat16_as_ushort(h0) | ((uint32_t)__bfloat16_as_ushort(h1) << 16),
                (uint32_t)__bfloat16_as_ushort(h2) | ((uint32_t)__bfloat16_as_ushort(h3) << 16));
            *(uint2*)(aLo + off) = make_uint2(
                (uint32_t)__bfloat16_as_ushort(l0) | ((uint32_t)__bfloat16_as_ushort(l1) << 16),
                (uint32_t)__bfloat16_as_ushort(l2) | ((uint32_t)__bfloat16_as_ushort(l3) << 16));
        }
        #pragma unroll
        for (int i = 0; i < 4; i++) {
            int f = i * 256 + tid, pl = f >> 9, fr = f & 511, row = fr >> 2, q = fr & 3;
            *(uint4*)((pl ? bLo : bHi) + row * 80 + q * 16) = rb[i];
        }
    }
    __syncthreads();

    #pragma unroll 1
    for (int kt = 0; kt < 16; ++kt) {
        const int s = kt & 1;
        // ---- prefetch next tile into registers ----
        if (kt < 15) {
            const float* Ap = Ab + (kt + 1) * 32;
            #pragma unroll
            for (int i = 0; i < 4; i++)
                ra[i] = *(const float4*)(Ap + (size_t)(arow + i * 32) * HD + ac4 * 4);
            const unsigned short* Bp = Wb + (size_t)(kt + 1) * 32768;
            #pragma unroll
            for (int i = 0; i < 4; i++) {
                int f = i * 256 + tid, pl = f >> 9, fr = f & 511, row = fr >> 2, q = fr & 3;
                rb[i] = *(const uint4*)(Bp + (size_t)pl * 16384 + (size_t)(bn + row) * 32 + q * 8);
            }
        }
        // ---- compute on buffer s ----
        {
            char* aHi = dsm + s * BUFB;
            char* aLo = aHi + PLANE;
            char* bHi = aHi + 2 * PLANE;
            char* bLo = aHi + 3 * PLANE;
            #pragma unroll
            for (int ks = 0; ks < 2; ++ks) {
                const int kb = ks * 32;
                uint32_t ah[2][4], al[2][4];
                #pragma unroll
                for (int i = 0; i < 2; i++) {
                    uint32_t ro = (wm + 16 * i + g) * 80 + kb + t4 * 4;
                    ah[i][0] = *(const uint32_t*)(aHi + ro);
                    ah[i][1] = *(const uint32_t*)(aHi + ro + 640);
                    ah[i][2] = *(const uint32_t*)(aHi + ro + 16);
                    ah[i][3] = *(const uint32_t*)(aHi + ro + 656);
                    al[i][0] = *(const uint32_t*)(aLo + ro);
                    al[i][1] = *(const uint32_t*)(aLo + ro + 640);
                    al[i][2] = *(const uint32_t*)(aLo + ro + 16);
                    al[i][3] = *(const uint32_t*)(aLo + ro + 656);
                }
                #pragma unroll
                for (int j = 0; j < 8; j++) {
                    uint32_t bo = (wn + 8 * j + g) * 80 + kb + t4 * 4;
                    uint32_t bh0 = *(const uint32_t*)(bHi + bo);
                    uint32_t bh1 = *(const uint32_t*)(bHi + bo + 16);
                    uint32_t bl0 = *(const uint32_t*)(bLo + bo);
                    uint32_t bl1 = *(const uint32_t*)(bLo + bo + 16);
                    #pragma unroll
                    for (int i = 0; i < 2; i++) {
                        mma16816(acc[i][j], ah[i], bh0, bh1);
                        mma16816(acc[i][j], al[i], bh0, bh1);
                        mma16816(acc[i][j], ah[i], bl0, bl1);
                    }
                }
            }
        }
        // ---- stage next tile into buffer 1-s ----
        if (kt < 15) {
            char* aHi = dsm + (1 - s) * BUFB;
            char* aLo = aHi + PLANE;
            char* bHi = aHi + 2 * PLANE;
            char* bLo = aHi + 3 * PLANE;
            #pragma unroll
            for (int i = 0; i < 4; i++) {
                float4 v = ra[i];
                __nv_bfloat16 h0 = __float2bfloat16(v.x), h1 = __float2bfloat16(v.y),
                              h2 = __float2bfloat16(v.z), h3 = __float2bfloat16(v.w);
                __nv_bfloat16 l0 = __float2bfloat16(v.x - __bfloat162float(h0));
                __nv_bfloat16 l1 = __float2bfloat16(v.y - __bfloat162float(h1));
                __nv_bfloat16 l2 = __float2bfloat16(v.z - __bfloat162float(h2));
                __nv_bfloat16 l3 = __float2bfloat16(v.w - __bfloat162float(h3));
                uint32_t off = (arow + i * 32) * 80 + ac4 * 8;
                *(uint2*)(aHi + off) = make_uint2(
                    (uint32_t)__bfloat16_as_ushort(h0) | ((uint32_t)__bfloat16_as_ushort(h1) << 16),
                    (uint32_t)__bfloat16_as_ushort(h2) | ((uint32_t)__bfloat16_as_ushort(h3) << 16));
                *(uint2*)(aLo + off) = make_uint2(
                    (uint32_t)__bfloat16_as_ushort(l0) | ((uint32_t)__bfloat16_as_ushort(l1) << 16),
                    (uint32_t)__bfloat16_as_ushort(l2) | ((uint32_t)__bfloat16_as_ushort(l3) << 16));
            }
            #pragma unroll
            for (int i = 0; i < 4; i++) {
                int f = i * 256 + tid, pl = f >> 9, fr = f & 511, row = fr >> 2, q = fr & 3;
                *(uint4*)((pl ? bLo : bHi) + row * 80 + q * 16) = rb[i];
            }
        }
        __syncthreads();
    }

    // ---- epilogue: bias + relu, store float2 pairs ----
    #pragma unroll
    for (int i = 0; i < 2; i++) {
        #pragma unroll
        for (int j = 0; j < 8; j++) {
            int cb = wn + 8 * j + t4 * 2;
            float b0 = sBias[bn + cb], b1 = sBias[bn + cb + 1];
            float v0 = acc[i][j][0] + b0, v1 = acc[i][j][1] + b1;
            float v2 = acc[i][j][2] + b0, v3 = acc[i][j][3] + b1;
            v0 = v0 > 0.f ? v0 : 0.f; v1 = v1 > 0.f ? v1 : 0.f;
            v2 = v2 > 0.f ? v2 : 0.f; v3 = v3 > 0.f ? v3 : 0.f;
            int m0 = wm + 16 * i + g;
            *(float2*)(Ob + (size_t)m0 * HD + cb)       = make_float2(v0, v1);
            *(float2*)(Ob + (size_t)(m0 + 8) * HD + cb) = make_float2(v2, v3);
        }
    }
}

// ---------------- aggregation: a1[t] = sum_f c1n[t,f]*h0[f] -------------------
__global__ void agg1_kernel() {
    __shared__ float c1s[64];
    int t = threadIdx.x;
    if (t < 64) c1s[t] = g_c1n[t];
    __syncthreads();
    size_t off = ((size_t)blockIdx.x * 256 + t) << 2;
    float4 h[8];
    #pragma unroll
    for (int f = 0; f < 8; f++)
        h[f] = *(const float4*)(g_bufA + (size_t)f * SLAB + off);
    #pragma unroll
    for (int u = 0; u < 8; u++) {
        float4 s = make_float4(0.f, 0.f, 0.f, 0.f);
        #pragma unroll
        for (int f = 0; f < 8; f++) {
            float c = c1s[u * 8 + f];
            s.x = fmaf(c, h[f].x, s.x);
            s.y = fmaf(c, h[f].y, s.y);
            s.z = fmaf(c, h[f].z, s.z);
            s.w = fmaf(c, h[f].w, s.w);
        }
        *(float4*)(g_bufB + (size_t)u * SLAB + off) = s;
    }
}

// ---------------- output GEMM (SIMT f32x2): out = sum_f h1[f]@W2eff[f]+gbias --
__global__ __launch_bounds__(256)
void gemm_out_kernel(float* __restrict__ Out) {
    const int bm = blockIdx.x * 64;
    const int t  = threadIdx.x;
    const int tx = t & 15, ty = t >> 4;
    const int am = t >> 2,  ak  = (t & 3) << 2;
    const int bk = t >> 4,  bn4 = (t & 15) << 2;

    __shared__ __align__(16) float As[2][16][68];
    __shared__ __align__(16) float Bs[2][16][64];

    unsigned long long acc[4][2];
    #pragma unroll
    for (int i = 0; i < 4; i++) { acc[i][0] = 0ULL; acc[i][1] = 0ULL; }

    float4 ra, rb;
    ra = *(const float4*)(g_bufA + (size_t)(bm + am) * HD + ak);
    rb = *(const float4*)(g_w2p + bk * 64 + bn4);
    As[0][ak + 0][am] = ra.x; As[0][ak + 1][am] = ra.y;
    As[0][ak + 2][am] = ra.z; As[0][ak + 3][am] = ra.w;
    *(float4*)&Bs[0][bk][bn4] = rb;
    __syncthreads();

    #pragma unroll 1
    for (int ft = 0; ft < 256; ++ft) {
        const int s = ft & 1;
        if (ft < 255) {
            const int fn  = (ft + 1) >> 5;
            const int k0n = ((ft + 1) & 31) << 4;
            ra = *(const float4*)(g_bufA + (size_t)fn * SLAB + (size_t)(bm + am) * HD + k0n + ak);
            rb = *(const float4*)(g_w2p + fn * 32768 + (k0n + bk) * 64 + bn4);
        }
        #pragma unroll
        for (int k = 0; k < 16; ++k) {
            float4 a = *(const float4*)&As[s][k][ty * 4];
            ulonglong2 bb = *(const ulonglong2*)&Bs[s][k][tx * 4];
            float av[4] = {a.x, a.y, a.z, a.w};
            #pragma unroll
            for (int i = 0; i < 4; i++) {
                unsigned long long ad = pack2(av[i]);
                fma2(acc[i][0], ad, bb.x);
                fma2(acc[i][1], ad, bb.y);
            }
        }
        if (ft < 255) {
            const int sn = 1 - s;
            As[sn][ak + 0][am] = ra.x; As[sn][ak + 1][am] = ra.y;
            As[sn][ak + 2][am] = ra.z; As[sn][ak + 3][am] = ra.w;
            *(float4*)&Bs[sn][bk][bn4] = rb;
        }
        __syncthreads();
    }

    float gb[4];
    #pragma unroll
    for (int j = 0; j < 4; j++) gb[j] = g_gbias[tx * 4 + j];
    #pragma unroll
    for (int i = 0; i < 4; i++) {
        int m = bm + ty * 4 + i;
        float2 p0 = unpack2(acc[i][0]);
        float2 p1 = unpack2(acc[i][1]);
        float v[4] = {p0.x + gb[0], p0.y + gb[1], p1.x + gb[2], p1.y + gb[3]};
        #pragma unroll
        for (int j = 0; j < 4; j++) {
            int c = tx * 4 + j;
            if (c < NC) Out[(size_t)m * NC + c] = v[j];
        }
    }
}

// ---------------- launch ------------------------------------------------------
extern "C" void kernel_launch(void* const* d_in, const int* in_sizes, int n_in,
                              void* d_out, int out_size) {
    const float* x  = (const float*)d_in[0];
    const float* p1 = (const float*)d_in[1];
    const float* p2 = (const float*)d_in[2];
    const float* pf = (const float*)d_in[3];
    const float* W0 = (const float*)d_in[4];
    const float* b0 = (const float*)d_in[5];
    const float* W1 = (const float*)d_in[6];
    const float* b1 = (const float*)d_in[7];
    const float* W2 = (const float*)d_in[8];
    const float* b2 = (const float*)d_in[9];
    float* out = (float*)d_out;

    cudaFuncSetAttribute(gemm_tc_kernel, cudaFuncAttributeMaxDynamicSharedMemorySize, GEMM_SMEM);

    // fold policies + output-layer weights; split/transpose W0, W1 to bf16 hi/lo
    prep_small_kernel<<<1, 64>>>(p1, p2, pf, b2);
    prep_w2eff_kernel<<<1024, 256>>>(W2);
    conv_w_kernel<<<512, 256>>>(W0, W1);

    // stage A: h0[u] = relu(x @ W0[u] + b0[u]) -> g_bufA   (HMMA tensor cores)
    gemm_tc_kernel<<<dim3(128, 4, 8), 256, GEMM_SMEM>>>(x, 1, 0, b0);

    // aggregation: a1 = c1n-mix(h0) -> g_bufB
    agg1_kernel<<<8192, 256>>>();

    // stage C: h1[u] = relu(a1[u] @ W1[u] + b1[u]) -> g_bufA   (HMMA tensor cores)
    gemm_tc_kernel<<<dim3(128, 4, 8), 256, GEMM_SMEM>>>(nullptr, 0, 1, b1);

    // output: out = sum_f h1[f] @ W2eff[f] + gbias
    gemm_out_kernel<<<256, 256>>>(out);
}

// round 6
// speedup vs baseline: 2.2121x; 1.1504x over previous
#include <cuda_runtime.h>
#include <cuda_bf16.h>
#include <cstdint>

// Problem constants
#define BSZ 16384
#define HD  512
#define NC  62
#define UU  8
#define SLAB ((size_t)1 << 23)   // 16384*512 floats per unit

// ---------------- scratch (device globals; no allocation allowed) -------------
__device__ float g_bufA[(size_t)UU * BSZ * HD];   // 256 MB: h0, then h1 (packed u32 in stage C)
__device__ float g_bufB[(size_t)UU * BSZ * HD];   // 256 MB: a1
__device__ uint32_t g_w2b[(size_t)UU * 16 * 64 * 32];  // W2eff split/packed: [(f*16+kt)][n64][k32]
__device__ float g_c1n[64];                       // normalized policy1
__device__ float g_c2g[64];                       // g_j * normalized policy2
__device__ float g_gbias[64];                     // folded output bias
// packed split weights per (layer,u,ktile): hi plane [n=512][k=32] bf16, then lo
__device__ unsigned short g_wpk[(size_t)2 * 8 * 16 * 32768];   // 16 MB

// ---------------- helpers -----------------------------------------------------
__device__ __forceinline__ uint32_t smem_to_u32(const void* p) {
    uint32_t a;
    asm("{ .reg .u64 t; cvta.to.shared.u64 t, %1; cvt.u32.u64 %0, t; }" : "=r"(a) : "l"(p));
    return a;
}
__device__ __forceinline__ void ldsm4(uint32_t* r, uint32_t addr) {
    asm volatile("ldmatrix.sync.aligned.m8n8.x4.shared.b16 {%0,%1,%2,%3}, [%4];"
        : "=r"(r[0]), "=r"(r[1]), "=r"(r[2]), "=r"(r[3]) : "r"(addr));
}
__device__ __forceinline__ void mma16816(float* c, const uint32_t* a,
                                         uint32_t b0, uint32_t b1) {
    asm volatile(
        "mma.sync.aligned.m16n8k16.row.col.f32.bf16.bf16.f32 "
        "{%0,%1,%2,%3}, {%4,%5,%6,%7}, {%8,%9}, {%0,%1,%2,%3};"
        : "+f"(c[0]), "+f"(c[1]), "+f"(c[2]), "+f"(c[3])
        : "r"(a[0]), "r"(a[1]), "r"(a[2]), "r"(a[3]), "r"(b0), "r"(b1));
}
__device__ __forceinline__ uint32_t packsplit(float v) {
    __nv_bfloat16 h = __float2bfloat16(v);
    __nv_bfloat16 l = __float2bfloat16(v - __bfloat162float(h));
    return (uint32_t)__bfloat16_as_ushort(h) | ((uint32_t)__bfloat16_as_ushort(l) << 16);
}

// ---------------- prep: tiny policy/bias folding ------------------------------
__global__ void prep_small_kernel(const float* __restrict__ p1,
                                  const float* __restrict__ p2,
                                  const float* __restrict__ pf,
                                  const float* __restrict__ b2) {
    __shared__ float gs[8];
    int t = threadIdx.x;
    if (t == 0) {
        float d = 0.f;
        for (int j = 0; j < 8; j++) d += pf[j];
        float inv = d > 0.f ? 1.f / d : 1.f;
        float acc = 1.f;
        for (int j = 7; j >= 0; --j) { acc *= inv; gs[j] = pf[j] * acc; }
    }
    __syncthreads();
    if (t < 8) {
        float r1 = 0.f, r2 = 0.f;
        for (int f = 0; f < 8; f++) { r1 += p1[t * 8 + f]; r2 += p2[t * 8 + f]; }
        float i1 = r1 > 0.f ? 1.f / r1 : 1.f;
        float i2 = r2 > 0.f ? 1.f / r2 : 1.f;
        for (int f = 0; f < 8; f++) {
            g_c1n[t * 8 + f] = p1[t * 8 + f] * i1;
            g_c2g[t * 8 + f] = gs[t] * p2[t * 8 + f] * i2;
        }
    }
    if (t < 62) {
        float s = 0.f;
        for (int j = 0; j < 8; j++) s += gs[j] * b2[j * NC + t];
        g_gbias[t] = s;
    } else if (t < 64) {
        g_gbias[t] = 0.f;
    }
}

// W2eff[f][k][n] = sum_j c2g[j][f]*W2[j][k][n]; split to bf16 hi/lo packed u32,
// transposed to [(f*16+kt)][n(64)][k(32)].
__global__ void prep_w2eff_kernel(const float* __restrict__ W2) {
    int idx = blockIdx.x * 256 + threadIdx.x;    // 262144
    int f = idx >> 15;
    int k512 = (idx >> 6) & 511;
    int n = idx & 63;
    float s = 0.f;
    if (n < NC) {
        #pragma unroll
        for (int j = 0; j < 8; j++)
            s = fmaf(g_c2g[j * 8 + f], W2[((size_t)(j * 512) + k512) * NC + n], s);
    }
    int kt = k512 >> 5, kk = k512 & 31;
    g_w2b[((size_t)(f * 16 + kt) * 64 + n) * 32 + kk] = packsplit(s);
}

// ---------------- weight transpose + bf16 hi/lo split --------------------------
__global__ void conv_w_kernel(const float* __restrict__ W0, const float* __restrict__ W1) {
    int idx = blockIdx.x * 256 + threadIdx.x;   // 131072 total
    int n  = idx & 511;
    int r  = idx >> 9;          // (l*8+u)*16 + kt, < 256
    int kt = r & 15;
    int ug = r >> 4;
    const float* W = (ug >= 8 ? W1 : W0) + ((size_t)(ug & 7) << 18);
    unsigned short hv[32], lv[32];
    #pragma unroll 8
    for (int i = 0; i < 32; i++) {
        float x = W[(size_t)(kt * 32 + i) * 512 + n];
        __nv_bfloat16 h = __float2bfloat16(x);
        float res = x - __bfloat162float(h);
        __nv_bfloat16 l = __float2bfloat16(res);
        hv[i] = __bfloat16_as_ushort(h);
        lv[i] = __bfloat16_as_ushort(l);
    }
    unsigned short* dst = g_wpk + (size_t)r * 32768 + n * 32;
    #pragma unroll
    for (int i = 0; i < 4; i++) {
        *(uint4*)(dst + i * 8)          = *(uint4*)(hv + i * 8);
        *(uint4*)(dst + 16384 + i * 8)  = *(uint4*)(lv + i * 8);
    }
}

// =========== HMMA bf16-split GEMM: C[u] = relu(A[u] @ W[u] + b[u]) ============
// M=16384, N=512, K=512. BM=128, BN=128, BK=32. 8 warps 4x2, warp tile 32x64.
// Fragments loaded via ldmatrix.x4; SMEM rows stride 80 B (bank-conflict-free).
#define PLANE 10240                 // 128 rows * 80 B
#define BUFB  (4 * PLANE)           // Ahi, Alo, Bhi, Blo
#define GEMM_SMEM (2 * BUFB)        // 81920

__global__ __launch_bounds__(256, 2)
void gemm_tc_kernel(const float* __restrict__ Aext, int useExt, int layer,
                    const float* __restrict__ bias, int packOut) {
    extern __shared__ __align__(16) char dsm[];
    __shared__ float sBias[512];

    const int tid = threadIdx.x;
    const int wid = tid >> 5, lane = tid & 31;
    const int g = lane >> 2, t4 = lane & 3;
    const int wm = (wid >> 1) * 32;
    const int wn = (wid & 1) * 64;
    const int u  = blockIdx.z;
    const int bm = blockIdx.x * 128;
    const int bn = blockIdx.y * 128;
    const uint32_t sb = smem_to_u32(dsm);

    // ldmatrix lane decodes
    const int la  = (lane & 7) + ((lane >> 3) & 1) * 8;   // A row within frag
    const int lk  = (lane >> 4) * 16;                     // A k-byte
    const int lbn = (lane & 7) + ((lane >> 4) & 1) * 8;   // B n within pair
    const int lbk = ((lane >> 3) & 1) * 16;               // B k-byte

    const float* Ab = useExt ? (Aext + (size_t)bm * HD)
                             : ((const float*)g_bufB + (size_t)u * SLAB + (size_t)bm * HD);
    const unsigned short* Wb = g_wpk + (size_t)((layer * 8 + u) * 16) * 32768;
    float* Ob = g_bufA + (size_t)u * SLAB + (size_t)bm * HD + bn;

    ((float2*)sBias)[tid] = ((const float2*)(bias + u * HD))[tid];

    float acc[2][8][4];
    #pragma unroll
    for (int i = 0; i < 2; i++)
        #pragma unroll
        for (int j = 0; j < 8; j++)
            #pragma unroll
            for (int q = 0; q < 4; q++) acc[i][j][q] = 0.f;

    float4 ra[4];
    uint4  rb[4];
    const int arow = tid >> 3, ac4 = tid & 7;

    // ---- prologue: tile 0 ----
    #pragma unroll
    for (int i = 0; i < 4; i++)
        ra[i] = *(const float4*)(Ab + (size_t)(arow + i * 32) * HD + ac4 * 4);
    #pragma unroll
    for (int i = 0; i < 4; i++) {
        int f = i * 256 + tid, pl = f >> 9, fr = f & 511, row = fr >> 2, q = fr & 3;
        rb[i] = *(const uint4*)(Wb + (size_t)pl * 16384 + (size_t)(bn + row) * 32 + q * 8);
    }
    {
        char* aHi = dsm;             char* aLo = dsm + PLANE;
        char* bHi = dsm + 2 * PLANE; char* bLo = dsm + 3 * PLANE;
        #pragma unroll
        for (int i = 0; i < 4; i++) {
            float4 v = ra[i];
            uint32_t off = (arow + i * 32) * 80 + ac4 * 8;
            uint32_t p0 = packsplit(v.x), p1 = packsplit(v.y),
                     p2 = packsplit(v.z), p3 = packsplit(v.w);
            *(uint2*)(aHi + off) = make_uint2(__byte_perm(p0, p1, 0x5410),
                                              __byte_perm(p2, p3, 0x5410));
            *(uint2*)(aLo + off) = make_uint2(__byte_perm(p0, p1, 0x7632),
                                              __byte_perm(p2, p3, 0x7632));
        }
        #pragma unroll
        for (int i = 0; i < 4; i++) {
            int f = i * 256 + tid, pl = f >> 9, fr = f & 511, row = fr >> 2, q = fr & 3;
            *(uint4*)((pl ? bLo : bHi) + row * 80 + q * 16) = rb[i];
        }
    }
    __syncthreads();

    #pragma unroll 1
    for (int kt = 0; kt < 16; ++kt) {
        const int s = kt & 1;
        if (kt < 15) {
            const float* Ap = Ab + (kt + 1) * 32;
            #pragma unroll
            for (int i = 0; i < 4; i++)
                ra[i] = *(const float4*)(Ap + (size_t)(arow + i * 32) * HD + ac4 * 4);
            const unsigned short* Bp = Wb + (size_t)(kt + 1) * 32768;
            #pragma unroll
            for (int i = 0; i < 4; i++) {
                int f = i * 256 + tid, pl = f >> 9, fr = f & 511, row = fr >> 2, q = fr & 3;
                rb[i] = *(const uint4*)(Bp + (size_t)pl * 16384 + (size_t)(bn + row) * 32 + q * 8);
            }
        }
        // ---- compute on buffer s (ldmatrix fragments) ----
        {
            const uint32_t aHi = sb + s * BUFB;
            const uint32_t bHi = aHi + 2 * PLANE;
            #pragma unroll
            for (int ks = 0; ks < 2; ++ks) {
                const int kb = ks * 32;
                uint32_t ah[2][4], al[2][4];
                #pragma unroll
                for (int i = 0; i < 2; i++) {
                    uint32_t ad = aHi + (wm + 16 * i + la) * 80 + kb + lk;
                    ldsm4(ah[i], ad);
                    ldsm4(al[i], ad + PLANE);
                }
                #pragma unroll
                for (int jp = 0; jp < 4; jp++) {
                    uint32_t bd = bHi + (wn + 16 * jp + lbn) * 80 + kb + lbk;
                    uint32_t bh[4], bl[4];
                    ldsm4(bh, bd);
                    ldsm4(bl, bd + PLANE);
                    #pragma unroll
                    for (int jj = 0; jj < 2; jj++) {
                        const int j = 2 * jp + jj;
                        #pragma unroll
                        for (int i = 0; i < 2; i++) {
                            mma16816(acc[i][j], ah[i], bh[2 * jj], bh[2 * jj + 1]);
                            mma16816(acc[i][j], al[i], bh[2 * jj], bh[2 * jj + 1]);
                            mma16816(acc[i][j], ah[i], bl[2 * jj], bl[2 * jj + 1]);
                        }
                    }
                }
            }
        }
        // ---- stage next tile into buffer 1-s ----
        if (kt < 15) {
            char* aHi = dsm + (1 - s) * BUFB;
            char* aLo = aHi + PLANE;
            char* bHi = aHi + 2 * PLANE;
            char* bLo = aHi + 3 * PLANE;
            #pragma unroll
            for (int i = 0; i < 4; i++) {
                float4 v = ra[i];
                uint32_t off = (arow + i * 32) * 80 + ac4 * 8;
                uint32_t p0 = packsplit(v.x), p1 = packsplit(v.y),
                         p2 = packsplit(v.z), p3 = packsplit(v.w);
                *(uint2*)(aHi + off) = make_uint2(__byte_perm(p0, p1, 0x5410),
                                                  __byte_perm(p2, p3, 0x5410));
                *(uint2*)(aLo + off) = make_uint2(__byte_perm(p0, p1, 0x7632),
                                                  __byte_perm(p2, p3, 0x7632));
            }
            #pragma unroll
            for (int i = 0; i < 4; i++) {
                int f = i * 256 + tid, pl = f >> 9, fr = f & 511, row = fr >> 2, q = fr & 3;
                *(uint4*)((pl ? bLo : bHi) + row * 80 + q * 16) = rb[i];
            }
        }
        __syncthreads();
    }

    // ---- epilogue: bias + relu ----
    if (!packOut) {
        #pragma unroll
        for (int i = 0; i < 2; i++) {
            #pragma unroll
            for (int j = 0; j < 8; j++) {
                int cb = wn + 8 * j + t4 * 2;
                float b0 = sBias[bn + cb], b1 = sBias[bn + cb + 1];
                float v0 = acc[i][j][0] + b0, v1 = acc[i][j][1] + b1;
                float v2 = acc[i][j][2] + b0, v3 = acc[i][j][3] + b1;
                v0 = v0 > 0.f ? v0 : 0.f; v1 = v1 > 0.f ? v1 : 0.f;
                v2 = v2 > 0.f ? v2 : 0.f; v3 = v3 > 0.f ? v3 : 0.f;
                int m0 = wm + 16 * i + g;
                *(float2*)(Ob + (size_t)m0 * HD + cb)       = make_float2(v0, v1);
                *(float2*)(Ob + (size_t)(m0 + 8) * HD + cb) = make_float2(v2, v3);
            }
        }
    } else {
        uint32_t* Op = (uint32_t*)Ob;
        #pragma unroll
        for (int i = 0; i < 2; i++) {
            #pragma unroll
            for (int j = 0; j < 8; j++) {
                int cb = wn + 8 * j + t4 * 2;
                float b0 = sBias[bn + cb], b1 = sBias[bn + cb + 1];
                float v0 = acc[i][j][0] + b0, v1 = acc[i][j][1] + b1;
                float v2 = acc[i][j][2] + b0, v3 = acc[i][j][3] + b1;
                v0 = v0 > 0.f ? v0 : 0.f; v1 = v1 > 0.f ? v1 : 0.f;
                v2 = v2 > 0.f ? v2 : 0.f; v3 = v3 > 0.f ? v3 : 0.f;
                int m0 = wm + 16 * i + g;
                *(uint2*)(Op + (size_t)m0 * HD + cb)       = make_uint2(packsplit(v0), packsplit(v1));
                *(uint2*)(Op + (size_t)(m0 + 8) * HD + cb) = make_uint2(packsplit(v2), packsplit(v3));
            }
        }
    }
}

// ---------------- aggregation: a1[t] = sum_f c1n[t,f]*h0[f] -------------------
__global__ void agg1_kernel() {
    __shared__ float c1s[64];
    int t = threadIdx.x;
    if (t < 64) c1s[t] = g_c1n[t];
    __syncthreads();
    size_t off = ((size_t)blockIdx.x * 256 + t) << 2;
    float4 h[8];
    #pragma unroll
    for (int f = 0; f < 8; f++)
        h[f] = *(const float4*)(g_bufA + (size_t)f * SLAB + off);
    #pragma unroll
    for (int u = 0; u < 8; u++) {
        float4 s = make_float4(0.f, 0.f, 0.f, 0.f);
        #pragma unroll
        for (int f = 0; f < 8; f++) {
            float c = c1s[u * 8 + f];
            s.x = fmaf(c, h[f].x, s.x);
            s.y = fmaf(c, h[f].y, s.y);
            s.z = fmaf(c, h[f].z, s.z);
            s.w = fmaf(c, h[f].w, s.w);
        }
        *(float4*)(g_bufB + (size_t)u * SLAB + off) = s;
    }
}

// ============ HMMA output GEMM: out = sum_f h1[f] @ W2eff[f] + gbias ==========
// M=16384 (BM=64 -> 256 CTAs), N=64 (NC=62), K=4096 (8 f x 16 kt x 32).
// 8 warps: wm=(wid&3)*16, wn=(wid>>2)*32; warp tile 16x32. A packed hi/lo u32.
#define OPLANE 5120                 // 64 rows * 80 B
#define OBUF   (4 * OPLANE)
#define OUT_SMEM (2 * OBUF)         // 40960

__global__ __launch_bounds__(256, 2)
void gemm_out_tc(float* __restrict__ Out) {
    extern __shared__ __align__(16) char dsm[];
    const uint32_t sb = smem_to_u32(dsm);
    const int tid = threadIdx.x;
    const int wid = tid >> 5, lane = tid & 31;
    const int g = lane >> 2, t4 = lane & 3;
    const int wm = (wid & 3) * 16;
    const int wn = (wid >> 2) * 32;
    const int bm = blockIdx.x * 64;

    const int la  = (lane & 7) + ((lane >> 3) & 1) * 8;
    const int lk  = (lane >> 4) * 16;
    const int lbn = (lane & 7) + ((lane >> 4) & 1) * 8;
    const int lbk = ((lane >> 3) & 1) * 16;

    const uint32_t* Apk = (const uint32_t*)g_bufA;
    const int srow = tid >> 2, sq = tid & 3;   // staging: row 0..63, quarter

    float acc[4][4];
    #pragma unroll
    for (int j = 0; j < 4; j++)
        #pragma unroll
        for (int q = 0; q < 4; q++) acc[j][q] = 0.f;

    uint4 ra[2], rb[2];

    auto stage = [&](char* buf) {
        char* aHi = buf;              char* aLo = buf + OPLANE;
        char* bHi = buf + 2 * OPLANE; char* bLo = buf + 3 * OPLANE;
        uint32_t off = srow * 80 + sq * 16;
        *(uint4*)(aHi + off) = make_uint4(
            __byte_perm(ra[0].x, ra[0].y, 0x5410), __byte_perm(ra[0].z, ra[0].w, 0x5410),
            __byte_perm(ra[1].x, ra[1].y, 0x5410), __byte_perm(ra[1].z, ra[1].w, 0x5410));
        *(uint4*)(aLo + off) = make_uint4(
            __byte_perm(ra[0].x, ra[0].y, 0x7632), __byte_perm(ra[0].z, ra[0].w, 0x7632),
            __byte_perm(ra[1].x, ra[1].y, 0x7632), __byte_perm(ra[1].z, ra[1].w, 0x7632));
        *(uint4*)(bHi + off) = make_uint4(
            __byte_perm(rb[0].x, rb[0].y, 0x5410), __byte_perm(rb[0].z, rb[0].w, 0x5410),
            __byte_perm(rb[1].x, rb[1].y, 0x5410), __byte_perm(rb[1].z, rb[1].w, 0x5410));
        *(uint4*)(bLo + off) = make_uint4(
            __byte_perm(rb[0].x, rb[0].y, 0x7632), __byte_perm(rb[0].z, rb[0].w, 0x7632),
            __byte_perm(rb[1].x, rb[1].y, 0x7632), __byte_perm(rb[1].z, rb[1].w, 0x7632));
    };
    auto fetch = [&](int it) {
        int f = it >> 4, kt = it & 15;
        const uint32_t* As = Apk + (size_t)f * SLAB + (size_t)(bm + srow) * HD + kt * 32 + sq * 8;
        ra[0] = *(const uint4*)As;
        ra[1] = *(const uint4*)(As + 4);
        const uint32_t* Bs = g_w2b + ((size_t)(f * 16 + kt) * 64 + srow) * 32 + sq * 8;
        rb[0] = *(const uint4*)Bs;
        rb[1] = *(const uint4*)(Bs + 4);
    };

    fetch(0);
    stage(dsm);
    __syncthreads();

    #pragma unroll 1
    for (int it = 0; it < 128; ++it) {
        const int s = it & 1;
        if (it < 127) fetch(it + 1);
        {
            const uint32_t aHi = sb + s * OBUF;
            const uint32_t bHi = aHi + 2 * OPLANE;
            #pragma unroll
            for (int ks = 0; ks < 2; ++ks) {
                const int kb = ks * 32;
                uint32_t ah[4], al[4];
                uint32_t ad = aHi + (wm + la) * 80 + kb + lk;
                ldsm4(ah, ad);
                ldsm4(al, ad + OPLANE);
                #pragma unroll
                for (int jp = 0; jp < 2; jp++) {
                    uint32_t bd = bHi + (wn + 16 * jp + lbn) * 80 + kb + lbk;
                    uint32_t bh[4], bl[4];
                    ldsm4(bh, bd);
                    ldsm4(bl, bd + OPLANE);
                    #pragma unroll
                    for (int jj = 0; jj < 2; jj++) {
                        const int j = 2 * jp + jj;
                        mma16816(acc[j], ah, bh[2 * jj], bh[2 * jj + 1]);
                        mma16816(acc[j], al, bh[2 * jj], bh[2 * jj + 1]);
                        mma16816(acc[j], ah, bl[2 * jj], bl[2 * jj + 1]);
                    }
                }
            }
        }
        if (it < 127) stage(dsm + (1 - s) * OBUF);
        __syncthreads();
    }

    // epilogue: + gbias, store (cols < NC)
    #pragma unroll
    for (int j = 0; j < 4; j++) {
        int c = wn + 8 * j + 2 * t4;
        float b0 = g_gbias[c], b1 = g_gbias[c + 1];
        int m0 = bm + wm + g;
        float v0 = acc[j][0] + b0, v1 = acc[j][1] + b1;
        float v2 = acc[j][2] + b0, v3 = acc[j][3] + b1;
        if (c < NC)     Out[(size_t)m0 * NC + c]           = v0;
        if (c + 1 < NC) Out[(size_t)m0 * NC + c + 1]       = v1;
        if (c < NC)     Out[(size_t)(m0 + 8) * NC + c]     = v2;
        if (c + 1 < NC) Out[(size_t)(m0 + 8) * NC + c + 1] = v3;
    }
}

// ---------------- launch ------------------------------------------------------
extern "C" void kernel_launch(void* const* d_in, const int* in_sizes, int n_in,
                              void* d_out, int out_size) {
    const float* x  = (const float*)d_in[0];
    const float* p1 = (const float*)d_in[1];
    const float* p2 = (const float*)d_in[2];
    const float* pf = (const float*)d_in[3];
    const float* W0 = (const float*)d_in[4];
    const float* b0 = (const float*)d_in[5];
    const float* W1 = (const float*)d_in[6];
    const float* b1 = (const float*)d_in[7];
    const float* W2 = (const float*)d_in[8];
    const float* b2 = (const float*)d_in[9];
    float* out = (float*)d_out;

    cudaFuncSetAttribute(gemm_tc_kernel, cudaFuncAttributeMaxDynamicSharedMemorySize, GEMM_SMEM);
    cudaFuncSetAttribute(gemm_out_tc, cudaFuncAttributeMaxDynamicSharedMemorySize, OUT_SMEM);

    // fold policies + output-layer weights; split/transpose W0, W1 to bf16 hi/lo
    prep_small_kernel<<<1, 64>>>(p1, p2, pf, b2);
    prep_w2eff_kernel<<<1024, 256>>>(W2);
    conv_w_kernel<<<512, 256>>>(W0, W1);

    // stage A: h0[u] = relu(x @ W0[u] + b0[u]) -> g_bufA fp32
    gemm_tc_kernel<<<dim3(128, 4, 8), 256, GEMM_SMEM>>>(x, 1, 0, b0, 0);

    // aggregation: a1 = c1n-mix(h0) -> g_bufB
    agg1_kernel<<<8192, 256>>>();

    // stage C: h1[u] = relu(a1[u] @ W1[u] + b1[u]) -> g_bufA packed bf16 hi/lo
    gemm_tc_kernel<<<dim3(128, 4, 8), 256, GEMM_SMEM>>>(nullptr, 0, 1, b1, 1);

    // output: out = sum_f h1[f] @ W2eff[f] + gbias  (HMMA)
    gemm_out_tc<<<256, 256, OUT_SMEM>>>(out);
}

// round 7
// speedup vs baseline: 2.9354x; 1.3270x over previous
#include <cuda_runtime.h>
#include <cuda_fp16.h>
#include <cstdint>

// Problem constants
#define BSZ 16384
#define HD  512
#define NC  62
#define UU  8
#define SLAB  ((size_t)BSZ * HD)   // per-unit plane elems (8M)

// ---------------- scratch (device globals; no allocation allowed) -------------
__device__ __align__(16) float  g_bufA[(size_t)UU * BSZ * HD];  // h0 fp32 (256 MB)
__device__ __align__(16) __half g_xh[(size_t)BSZ * HD];
__device__ __align__(16) __half g_xl[(size_t)BSZ * HD];
__device__ __align__(16) __half g_a1h[(size_t)UU * BSZ * HD];
__device__ __align__(16) __half g_a1l[(size_t)UU * BSZ * HD];
__device__ __align__(16) __half g_h1h[(size_t)UU * BSZ * HD];
__device__ __align__(16) __half g_h1l[(size_t)UU * BSZ * HD];
__device__ __align__(16) __half g_wh[(size_t)2 * 8 * 16 * 512 * 32];  // [(l*8+u)][kt][n512][k32]
__device__ __align__(16) __half g_w2h[(size_t)8 * 16 * 64 * 32];      // [(f*16+kt)][n64][k32]
__device__ float g_c1n[64];
__device__ float g_c2g[64];
__device__ float g_gbias[64];

// ---------------- helpers -----------------------------------------------------
__device__ __forceinline__ uint32_t smem_to_u32(const void* p) {
    uint32_t a;
    asm("{ .reg .u64 t; cvta.to.shared.u64 t, %1; cvt.u32.u64 %0, t; }" : "=r"(a) : "l"(p));
    return a;
}
__device__ __forceinline__ void ldsm4(uint32_t* r, uint32_t addr) {
    asm volatile("ldmatrix.sync.aligned.m8n8.x4.shared.b16 {%0,%1,%2,%3}, [%4];"
        : "=r"(r[0]), "=r"(r[1]), "=r"(r[2]), "=r"(r[3]) : "r"(addr));
}
__device__ __forceinline__ void mma16816(float* c, const uint32_t* a,
                                         uint32_t b0, uint32_t b1) {
    asm volatile(
        "mma.sync.aligned.m16n8k16.row.col.f32.f16.f16.f32 "
        "{%0,%1,%2,%3}, {%4,%5,%6,%7}, {%8,%9}, {%0,%1,%2,%3};"
        : "+f"(c[0]), "+f"(c[1]), "+f"(c[2]), "+f"(c[3])
        : "r"(a[0]), "r"(a[1]), "r"(a[2]), "r"(a[3]), "r"(b0), "r"(b1));
}
__device__ __forceinline__ void cpa16(uint32_t d, const void* s) {
    asm volatile("cp.async.cg.shared.global [%0], [%1], 16;" :: "r"(d), "l"(s));
}
#define CP_COMMIT() asm volatile("cp.async.commit_group;" ::: "memory")

__device__ __forceinline__ uint32_t pkh(float a, float b) {
    __half ha = __float2half(a), hb = __float2half(b);
    return (uint32_t)__half_as_ushort(ha) | ((uint32_t)__half_as_ushort(hb) << 16);
}
__device__ __forceinline__ float resh(float v) {
    return v - __half2float(__float2half(v));
}

// ---------------- prep: tiny policy/bias folding ------------------------------
__global__ void prep_small_kernel(const float* __restrict__ p1,
                                  const float* __restrict__ p2,
                                  const float* __restrict__ pf,
                                  const float* __restrict__ b2) {
    __shared__ float gs[8];
    int t = threadIdx.x;
    if (t == 0) {
        float d = 0.f;
        for (int j = 0; j < 8; j++) d += pf[j];
        float inv = d > 0.f ? 1.f / d : 1.f;
        float acc = 1.f;
        for (int j = 7; j >= 0; --j) { acc *= inv; gs[j] = pf[j] * acc; }
    }
    __syncthreads();
    if (t < 8) {
        float r1 = 0.f, r2 = 0.f;
        for (int f = 0; f < 8; f++) { r1 += p1[t * 8 + f]; r2 += p2[t * 8 + f]; }
        float i1 = r1 > 0.f ? 1.f / r1 : 1.f;
        float i2 = r2 > 0.f ? 1.f / r2 : 1.f;
        for (int f = 0; f < 8; f++) {
            g_c1n[t * 8 + f] = p1[t * 8 + f] * i1;
            g_c2g[t * 8 + f] = gs[t] * p2[t * 8 + f] * i2;
        }
    }
    if (t < 62) {
        float s = 0.f;
        for (int j = 0; j < 8; j++) s += gs[j] * b2[j * NC + t];
        g_gbias[t] = s;
    } else if (t < 64) {
        g_gbias[t] = 0.f;
    }
}

// W2eff[f][k][n] = sum_j c2g[j][f]*W2[j][k][n] -> fp16, layout [(f*16+kt)][n64][k32]
__global__ void prep_w2eff_kernel(const float* __restrict__ W2) {
    int idx = blockIdx.x * 256 + threadIdx.x;    // 262144
    int f = idx >> 15;
    int k512 = (idx >> 6) & 511;
    int n = idx & 63;
    float s = 0.f;
    if (n < NC) {
        #pragma unroll
        for (int j = 0; j < 8; j++)
            s = fmaf(g_c2g[j * 8 + f], W2[((size_t)(j * 512) + k512) * NC + n], s);
    }
    int kt = k512 >> 5, kk = k512 & 31;
    g_w2h[((size_t)(f * 16 + kt) * 64 + n) * 32 + kk] = __float2half(s);
}

// W0, W1 transpose -> fp16, layout [(l*8+u)][kt][n512][k32]
__global__ void conv_w_kernel(const float* __restrict__ W0, const float* __restrict__ W1) {
    int idx = blockIdx.x * 256 + threadIdx.x;   // 131072 total
    int n  = idx & 511;
    int r  = idx >> 9;          // (l*8+u)*16 + kt
    int kt = r & 15;
    int ug = r >> 4;
    const float* W = (ug >= 8 ? W1 : W0) + ((size_t)(ug & 7) << 18);
    unsigned short hv[32];
    #pragma unroll 8
    for (int i = 0; i < 32; i++)
        hv[i] = __half_as_ushort(__float2half(W[(size_t)(kt * 32 + i) * 512 + n]));
    __half* dst = g_wh + ((size_t)r * 512 + n) * 32;
    #pragma unroll
    for (int i = 0; i < 4; i++)
        *(uint4*)(dst + i * 8) = *(uint4*)(hv + i * 8);
}

// x -> fp16 hi/lo planes
__global__ void conv_x_kernel(const float* __restrict__ x) {
    size_t off = ((size_t)blockIdx.x * 256 + threadIdx.x) << 2;
    float4 v = *(const float4*)(x + off);
    *(uint2*)(g_xh + off) = make_uint2(pkh(v.x, v.y), pkh(v.z, v.w));
    *(uint2*)(g_xl + off) = make_uint2(pkh(resh(v.x), resh(v.y)),
                                       pkh(resh(v.z), resh(v.w)));
}

// =========== fp16 2-product HMMA GEMM: C[u] = relu(A[u] @ W[u] + b[u]) ========
// M=16384, N=512, K=512. BM=128, BN=128, BK=32. 8 warps 4x2, warp tile 32x64.
// SMEM: per stage Ahi/Alo/B planes, 128 rows x 80 B each (bank-conflict-free).
#define PLANE 10240
#define STG   (3 * PLANE)
#define GEMM_SMEM (2 * STG)     // 61440

__global__ __launch_bounds__(256, 2)
void gemm_fp16(int srcSel, int layer, const float* __restrict__ bias, int packOut) {
    extern __shared__ __align__(16) char dsm[];
    __shared__ float sBias[512];
    const uint32_t sdyn = smem_to_u32(dsm);

    const int tid = threadIdx.x;
    const int wid = tid >> 5, lane = tid & 31;
    const int g = lane >> 2, t4 = lane & 3;
    const int wm = (wid >> 1) * 32;
    const int wn = (wid & 1) * 64;
    const int u  = blockIdx.z;
    const int bm = blockIdx.x * 128;
    const int bn = blockIdx.y * 128;

    // ldmatrix lane decodes (validated R5/R6)
    const int la  = (lane & 7) + ((lane >> 3) & 1) * 8;
    const int lk  = (lane >> 4) * 16;
    const int lbn = (lane & 7) + ((lane >> 4) & 1) * 8;
    const int lbk = ((lane >> 3) & 1) * 16;

    const __half* AhU;
    const __half* AlU;
    if (srcSel == 0) { AhU = g_xh; AlU = g_xl; }
    else { AhU = g_a1h + (size_t)u * SLAB; AlU = g_a1l + (size_t)u * SLAB; }
    AhU += (size_t)bm * HD;
    AlU += (size_t)bm * HD;
    const __half* Wb = g_wh + (size_t)(layer * 8 + u) * 262144;

    ((float2*)sBias)[tid] = ((const float2*)(bias + u * HD))[tid];

    float acc[2][8][4];
    #pragma unroll
    for (int i = 0; i < 2; i++)
        #pragma unroll
        for (int j = 0; j < 8; j++)
            #pragma unroll
            for (int q = 0; q < 4; q++) acc[i][j][q] = 0.f;

    const int r0 = tid >> 2, q0 = tid & 3;

    auto issue = [&](int kt, int bufI) {
        uint32_t sbuf = sdyn + bufI * STG;
        const __half* Ahp = AhU + kt * 32;
        const __half* Alp = AlU + kt * 32;
        const __half* Bp  = Wb + (size_t)kt * 16384 + (size_t)bn * 32;
        cpa16(sbuf + r0 * 80 + q0 * 16,                Ahp + (size_t)r0 * HD + q0 * 8);
        cpa16(sbuf + (r0 + 64) * 80 + q0 * 16,         Ahp + (size_t)(r0 + 64) * HD + q0 * 8);
        cpa16(sbuf + PLANE + r0 * 80 + q0 * 16,        Alp + (size_t)r0 * HD + q0 * 8);
        cpa16(sbuf + PLANE + (r0 + 64) * 80 + q0 * 16, Alp + (size_t)(r0 + 64) * HD + q0 * 8);
        cpa16(sbuf + 2 * PLANE + r0 * 80 + q0 * 16,        Bp + r0 * 32 + q0 * 8);
        cpa16(sbuf + 2 * PLANE + (r0 + 64) * 80 + q0 * 16, Bp + (r0 + 64) * 32 + q0 * 8);
        CP_COMMIT();
    };

    issue(0, 0);

    #pragma unroll 1
    for (int kt = 0; kt < 16; ++kt) {
        const int s = kt & 1;
        if (kt < 15) {
            issue(kt + 1, 1 - s);
            asm volatile("cp.async.wait_group 1;" ::: "memory");
        } else {
            asm volatile("cp.async.wait_group 0;" ::: "memory");
        }
        __syncthreads();
        {
            const uint32_t aH = sdyn + s * STG;
            const uint32_t aL = aH + PLANE;
            const uint32_t bB = aH + 2 * PLANE;
            #pragma unroll
            for (int k16 = 0; k16 < 2; k16++) {
                const int kb = k16 * 32;
                uint32_t ah0[4], ah1[4], al0[4], al1[4];
                ldsm4(ah0, aH + (wm + la) * 80 + kb + lk);
                ldsm4(ah1, aH + (wm + 16 + la) * 80 + kb + lk);
                ldsm4(al0, aL + (wm + la) * 80 + kb + lk);
                ldsm4(al1, aL + (wm + 16 + la) * 80 + kb + lk);
                #pragma unroll
                for (int jp = 0; jp < 4; jp++) {
                    uint32_t b[4];
                    ldsm4(b, bB + (wn + 16 * jp + lbn) * 80 + kb + lbk);
                    #pragma unroll
                    for (int jj = 0; jj < 2; jj++) {
                        const int j = 2 * jp + jj;
                        mma16816(acc[0][j], ah0, b[2 * jj], b[2 * jj + 1]);
                        mma16816(acc[0][j], al0, b[2 * jj], b[2 * jj + 1]);
                        mma16816(acc[1][j], ah1, b[2 * jj], b[2 * jj + 1]);
                        mma16816(acc[1][j], al1, b[2 * jj], b[2 * jj + 1]);
                    }
                }
            }
        }
        __syncthreads();
    }

    // ---- epilogue: bias + relu ----
    if (!packOut) {
        float* Ob = g_bufA + (size_t)u * SLAB + (size_t)bm * HD + bn;
        #pragma unroll
        for (int i = 0; i < 2; i++) {
            #pragma unroll
            for (int j = 0; j < 8; j++) {
                int cb = wn + 8 * j + t4 * 2;
                float b0 = sBias[bn + cb], b1 = sBias[bn + cb + 1];
                float v0 = acc[i][j][0] + b0, v1 = acc[i][j][1] + b1;
                float v2 = acc[i][j][2] + b0, v3 = acc[i][j][3] + b1;
                v0 = v0 > 0.f ? v0 : 0.f; v1 = v1 > 0.f ? v1 : 0.f;
                v2 = v2 > 0.f ? v2 : 0.f; v3 = v3 > 0.f ? v3 : 0.f;
                int m0 = wm + 16 * i + g;
                *(float2*)(Ob + (size_t)m0 * HD + cb)       = make_float2(v0, v1);
                *(float2*)(Ob + (size_t)(m0 + 8) * HD + cb) = make_float2(v2, v3);
            }
        }
    } else {
        __half* OH = g_h1h + (size_t)u * SLAB + (size_t)bm * HD + bn;
        __half* OL = g_h1l + (size_t)u * SLAB + (size_t)bm * HD + bn;
        #pragma unroll
        for (int i = 0; i < 2; i++) {
            #pragma unroll
            for (int j = 0; j < 8; j++) {
                int cb = wn + 8 * j + t4 * 2;
                float b0 = sBias[bn + cb], b1 = sBias[bn + cb + 1];
                float v0 = acc[i][j][0] + b0, v1 = acc[i][j][1] + b1;
                float v2 = acc[i][j][2] + b0, v3 = acc[i][j][3] + b1;
                v0 = v0 > 0.f ? v0 : 0.f; v1 = v1 > 0.f ? v1 : 0.f;
                v2 = v2 > 0.f ? v2 : 0.f; v3 = v3 > 0.f ? v3 : 0.f;
                int m0 = wm + 16 * i + g;
                *(uint32_t*)(OH + (size_t)m0 * HD + cb)       = pkh(v0, v1);
                *(uint32_t*)(OL + (size_t)m0 * HD + cb)       = pkh(resh(v0), resh(v1));
                *(uint32_t*)(OH + (size_t)(m0 + 8) * HD + cb) = pkh(v2, v3);
                *(uint32_t*)(OL + (size_t)(m0 + 8) * HD + cb) = pkh(resh(v2), resh(v3));
            }
        }
    }
}

// ---------------- aggregation: a1[t] = sum_f c1n[t,f]*h0[f], emit fp16 planes --
__global__ void agg1_kernel() {
    __shared__ float c1s[64];
    int t = threadIdx.x;
    if (t < 64) c1s[t] = g_c1n[t];
    __syncthreads();
    size_t off = ((size_t)blockIdx.x * 256 + t) << 2;
    float4 h[8];
    #pragma unroll
    for (int f = 0; f < 8; f++)
        h[f] = *(const float4*)(g_bufA + (size_t)f * SLAB + off);
    #pragma unroll
    for (int u = 0; u < 8; u++) {
        float4 s = make_float4(0.f, 0.f, 0.f, 0.f);
        #pragma unroll
        for (int f = 0; f < 8; f++) {
            float c = c1s[u * 8 + f];
            s.x = fmaf(c, h[f].x, s.x);
            s.y = fmaf(c, h[f].y, s.y);
            s.z = fmaf(c, h[f].z, s.z);
            s.w = fmaf(c, h[f].w, s.w);
        }
        *(uint2*)(g_a1h + (size_t)u * SLAB + off) = make_uint2(pkh(s.x, s.y), pkh(s.z, s.w));
        *(uint2*)(g_a1l + (size_t)u * SLAB + off) =
            make_uint2(pkh(resh(s.x), resh(s.y)), pkh(resh(s.z), resh(s.w)));
    }
}

// ============ fp16 output GEMM: out = sum_f h1[f] @ W2eff[f] + gbias ==========
// M=16384 (BM=64), N=64, K=4096 (8 f x 16 kt x 32). 8 warps, warp tile 16x32.
#define OPLANE 5120
#define OSTG   (3 * OPLANE)
#define OUT_SMEM (2 * OSTG)     // 30720

__global__ __launch_bounds__(256, 2)
void gemm_out_tc(float* __restrict__ Out) {
    extern __shared__ __align__(16) char dsm[];
    const uint32_t sdyn = smem_to_u32(dsm);
    const int tid = threadIdx.x;
    const int wid = tid >> 5, lane = tid & 31;
    const int g = lane >> 2, t4 = lane & 3;
    const int wm = (wid & 3) * 16;
    const int wn = (wid >> 2) * 32;
    const int bm = blockIdx.x * 64;

    const int la  = (lane & 7) + ((lane >> 3) & 1) * 8;
    const int lk  = (lane >> 4) * 16;
    const int lbn = (lane & 7) + ((lane >> 4) & 1) * 8;
    const int lbk = ((lane >> 3) & 1) * 16;

    float acc[4][4];
    #pragma unroll
    for (int j = 0; j < 4; j++)
        #pragma unroll
        for (int q = 0; q < 4; q++) acc[j][q] = 0.f;

    const int r0 = tid >> 2, q0 = tid & 3;   // 64 rows x 4 chunks

    auto issue = [&](int it, int bufI) {
        uint32_t sbuf = sdyn + bufI * OSTG;
        int f = it >> 4, kt = it & 15;
        const __half* Ahp = g_h1h + (size_t)f * SLAB + (size_t)bm * HD + kt * 32;
        const __half* Alp = g_h1l + (size_t)f * SLAB + (size_t)bm * HD + kt * 32;
        const __half* Bp  = g_w2h + (size_t)(f * 16 + kt) * 2048;
        cpa16(sbuf + r0 * 80 + q0 * 16,              Ahp + (size_t)r0 * HD + q0 * 8);
        cpa16(sbuf + OPLANE + r0 * 80 + q0 * 16,     Alp + (size_t)r0 * HD + q0 * 8);
        cpa16(sbuf + 2 * OPLANE + r0 * 80 + q0 * 16, Bp + r0 * 32 + q0 * 8);
        CP_COMMIT();
    };

    issue(0, 0);

    #pragma unroll 1
    for (int it = 0; it < 128; ++it) {
        const int s = it & 1;
        if (it < 127) {
            issue(it + 1, 1 - s);
            asm volatile("cp.async.wait_group 1;" ::: "memory");
        } else {
            asm volatile("cp.async.wait_group 0;" ::: "memory");
        }
        __syncthreads();
        {
            const uint32_t aH = sdyn + s * OSTG;
            const uint32_t aL = aH + OPLANE;
            const uint32_t bB = aH + 2 * OPLANE;
            #pragma unroll
            for (int k16 = 0; k16 < 2; k16++) {
                const int kb = k16 * 32;
                uint32_t ah[4], al[4];
                ldsm4(ah, aH + (wm + la) * 80 + kb + lk);
                ldsm4(al, aL + (wm + la) * 80 + kb + lk);
                #pragma unroll
                for (int jp = 0; jp < 2; jp++) {
                    uint32_t b[4];
                    ldsm4(b, bB + (wn + 16 * jp + lbn) * 80 + kb + lbk);
                    #pragma unroll
                    for (int jj = 0; jj < 2; jj++) {
                        const int j = 2 * jp + jj;
                        mma16816(acc[j], ah, b[2 * jj], b[2 * jj + 1]);
                        mma16816(acc[j], al, b[2 * jj], b[2 * jj + 1]);
                    }
                }
            }
        }
        __syncthreads();
    }

    // epilogue: + gbias, store (cols < NC)
    #pragma unroll
    for (int j = 0; j < 4; j++) {
        int c = wn + 8 * j + 2 * t4;
        float b0 = g_gbias[c], b1 = g_gbias[c + 1];
        int m0 = bm + wm + g;
        float v0 = acc[j][0] + b0, v1 = acc[j][1] + b1;
        float v2 = acc[j][2] + b0, v3 = acc[j][3] + b1;
        if (c < NC)     Out[(size_t)m0 * NC + c]           = v0;
        if (c + 1 < NC) Out[(size_t)m0 * NC + c + 1]       = v1;
        if (c < NC)     Out[(size_t)(m0 + 8) * NC + c]     = v2;
        if (c + 1 < NC) Out[(size_t)(m0 + 8) * NC + c + 1] = v3;
    }
}

// ---------------- launch ------------------------------------------------------
extern "C" void kernel_launch(void* const* d_in, const int* in_sizes, int n_in,
                              void* d_out, int out_size) {
    const float* x  = (const float*)d_in[0];
    const float* p1 = (const float*)d_in[1];
    const float* p2 = (const float*)d_in[2];
    const float* pf = (const float*)d_in[3];
    const float* W0 = (const float*)d_in[4];
    const float* b0 = (const float*)d_in[5];
    const float* W1 = (const float*)d_in[6];
    const float* b1 = (const float*)d_in[7];
    const float* W2 = (const float*)d_in[8];
    const float* b2 = (const float*)d_in[9];
    float* out = (float*)d_out;

    cudaFuncSetAttribute(gemm_fp16, cudaFuncAttributeMaxDynamicSharedMemorySize, GEMM_SMEM);
    cudaFuncSetAttribute(gemm_out_tc, cudaFuncAttributeMaxDynamicSharedMemorySize, OUT_SMEM);

    // fold policies + convert weights/inputs to fp16 layouts
    prep_small_kernel<<<1, 64>>>(p1, p2, pf, b2);
    prep_w2eff_kernel<<<1024, 256>>>(W2);
    conv_w_kernel<<<512, 256>>>(W0, W1);
    conv_x_kernel<<<8192, 256>>>(x);

    // stage A: h0[u] = relu(x @ W0[u] + b0[u]) -> g_bufA fp32
    gemm_fp16<<<dim3(128, 4, 8), 256, GEMM_SMEM>>>(0, 0, b0, 0);

    // aggregation: a1 = c1n-mix(h0) -> fp16 hi/lo planes
    agg1_kernel<<<8192, 256>>>();

    // stage C: h1[u] = relu(a1[u] @ W1[u] + b1[u]) -> fp16 hi/lo planes
    gemm_fp16<<<dim3(128, 4, 8), 256, GEMM_SMEM>>>(1, 1, b1, 1);

    // output: out = sum_f h1[f] @ W2eff[f] + gbias
    gemm_out_tc<<<256, 256, OUT_SMEM>>>(out);
}

// round 8
// speedup vs baseline: 4.5236x; 1.5410x over previous
#include <cuda_runtime.h>
#include <cuda_fp16.h>
#include <cstdint>

// Problem constants
#define BSZ 16384
#define HD  512
#define NC  62
#define UU  8
#define SLAB  ((size_t)BSZ * HD)   // per-unit plane elems (8M)

// ---------------- scratch (device globals; no allocation allowed) -------------
__device__ __align__(16) __half g_xh[(size_t)BSZ * HD];            // x fp16
__device__ __align__(16) __half g_h0[(size_t)UU * BSZ * HD];       // h0 fp16 (128 MB)
__device__ __align__(16) __half g_a1[(size_t)UU * BSZ * HD];       // a1 fp16
__device__ __align__(16) __half g_h1[(size_t)UU * BSZ * HD];       // h1 fp16
__device__ __align__(16) __half g_wh[(size_t)2 * 8 * 16 * 512 * 32];  // [(l*8+u)][kt][n512][k32]
__device__ __align__(16) __half g_w2h[(size_t)8 * 16 * 64 * 32];      // [(f*16+kt)][n64][k32]
__device__ float g_c1n[64];
__device__ float g_c2g[64];
__device__ float g_gbias[64];

// ---------------- helpers -----------------------------------------------------
__device__ __forceinline__ uint32_t smem_to_u32(const void* p) {
    uint32_t a;
    asm("{ .reg .u64 t; cvta.to.shared.u64 t, %1; cvt.u32.u64 %0, t; }" : "=r"(a) : "l"(p));
    return a;
}
__device__ __forceinline__ void ldsm4(uint32_t* r, uint32_t addr) {
    asm volatile("ldmatrix.sync.aligned.m8n8.x4.shared.b16 {%0,%1,%2,%3}, [%4];"
        : "=r"(r[0]), "=r"(r[1]), "=r"(r[2]), "=r"(r[3]) : "r"(addr));
}
__device__ __forceinline__ void mma16816(float* c, const uint32_t* a,
                                         uint32_t b0, uint32_t b1) {
    asm volatile(
        "mma.sync.aligned.m16n8k16.row.col.f32.f16.f16.f32 "
        "{%0,%1,%2,%3}, {%4,%5,%6,%7}, {%8,%9}, {%0,%1,%2,%3};"
        : "+f"(c[0]), "+f"(c[1]), "+f"(c[2]), "+f"(c[3])
        : "r"(a[0]), "r"(a[1]), "r"(a[2]), "r"(a[3]), "r"(b0), "r"(b1));
}
__device__ __forceinline__ void cpa16(uint32_t d, const void* s) {
    asm volatile("cp.async.cg.shared.global [%0], [%1], 16;" :: "r"(d), "l"(s));
}
#define CP_COMMIT() asm volatile("cp.async.commit_group;" ::: "memory")

__device__ __forceinline__ uint32_t pkh(float a, float b) {
    __half ha = __float2half(a), hb = __float2half(b);
    return (uint32_t)__half_as_ushort(ha) | ((uint32_t)__half_as_ushort(hb) << 16);
}

// ---------------- prep: tiny policy/bias folding ------------------------------
__global__ void prep_small_kernel(const float* __restrict__ p1,
                                  const float* __restrict__ p2,
                                  const float* __restrict__ pf,
                                  const float* __restrict__ b2) {
    __shared__ float gs[8];
    int t = threadIdx.x;
    if (t == 0) {
        float d = 0.f;
        for (int j = 0; j < 8; j++) d += pf[j];
        float inv = d > 0.f ? 1.f / d : 1.f;
        float acc = 1.f;
        for (int j = 7; j >= 0; --j) { acc *= inv; gs[j] = pf[j] * acc; }
    }
    __syncthreads();
    if (t < 8) {
        float r1 = 0.f, r2 = 0.f;
        for (int f = 0; f < 8; f++) { r1 += p1[t * 8 + f]; r2 += p2[t * 8 + f]; }
        float i1 = r1 > 0.f ? 1.f / r1 : 1.f;
        float i2 = r2 > 0.f ? 1.f / r2 : 1.f;
        for (int f = 0; f < 8; f++) {
            g_c1n[t * 8 + f] = p1[t * 8 + f] * i1;
            g_c2g[t * 8 + f] = gs[t] * p2[t * 8 + f] * i2;
        }
    }
    if (t < 62) {
        float s = 0.f;
        for (int j = 0; j < 8; j++) s += gs[j] * b2[j * NC + t];
        g_gbias[t] = s;
    } else if (t < 64) {
        g_gbias[t] = 0.f;
    }
}

// W2eff[f][k][n] = sum_j c2g[j][f]*W2[j][k][n] -> fp16, layout [(f*16+kt)][n64][k32]
__global__ void prep_w2eff_kernel(const float* __restrict__ W2) {
    int idx = blockIdx.x * 256 + threadIdx.x;    // 262144
    int f = idx >> 15;
    int k512 = (idx >> 6) & 511;
    int n = idx & 63;
    float s = 0.f;
    if (n < NC) {
        #pragma unroll
        for (int j = 0; j < 8; j++)
            s = fmaf(g_c2g[j * 8 + f], W2[((size_t)(j * 512) + k512) * NC + n], s);
    }
    int kt = k512 >> 5, kk = k512 & 31;
    g_w2h[((size_t)(f * 16 + kt) * 64 + n) * 32 + kk] = __float2half(s);
}

// W0, W1 transpose -> fp16, layout [(l*8+u)][kt][n512][k32]
__global__ void conv_w_kernel(const float* __restrict__ W0, const float* __restrict__ W1) {
    int idx = blockIdx.x * 256 + threadIdx.x;   // 131072 total
    int n  = idx & 511;
    int r  = idx >> 9;          // (l*8+u)*16 + kt
    int kt = r & 15;
    int ug = r >> 4;
    const float* W = (ug >= 8 ? W1 : W0) + ((size_t)(ug & 7) << 18);
    unsigned short hv[32];
    #pragma unroll 8
    for (int i = 0; i < 32; i++)
        hv[i] = __half_as_ushort(__float2half(W[(size_t)(kt * 32 + i) * 512 + n]));
    __half* dst = g_wh + ((size_t)r * 512 + n) * 32;
    #pragma unroll
    for (int i = 0; i < 4; i++)
        *(uint4*)(dst + i * 8) = *(uint4*)(hv + i * 8);
}

// x -> fp16
__global__ void conv_x_kernel(const float* __restrict__ x) {
    size_t off = ((size_t)blockIdx.x * 256 + threadIdx.x) << 2;
    float4 v = *(const float4*)(x + off);
    *(uint2*)(g_xh + off) = make_uint2(pkh(v.x, v.y), pkh(v.z, v.w));
}

// ============= fp16 HMMA GEMM: C[u] = relu(A[u] @ W[u] + b[u]) ================
// M=16384, N=512, K=512. BM=128, BN=128, BK=32. 8 warps 4x2, warp tile 32x64.
// SMEM per stage: A plane + B plane, 128 rows x 80 B each (bank-conflict-free).
#define PLANE 10240
#define STG   (2 * PLANE)
#define GEMM_SMEM (2 * STG)     // 40960

__global__ __launch_bounds__(256, 2)
void gemm_fp16(int srcSel, int layer, const float* __restrict__ bias, int outSel) {
    extern __shared__ __align__(16) char dsm[];
    __shared__ float sBias[512];
    const uint32_t sdyn = smem_to_u32(dsm);

    const int tid = threadIdx.x;
    const int wid = tid >> 5, lane = tid & 31;
    const int g = lane >> 2, t4 = lane & 3;
    const int wm = (wid >> 1) * 32;
    const int wn = (wid & 1) * 64;
    const int u  = blockIdx.z;
    const int bm = blockIdx.x * 128;
    const int bn = blockIdx.y * 128;

    // ldmatrix lane decodes (validated R5-R7)
    const int la  = (lane & 7) + ((lane >> 3) & 1) * 8;
    const int lk  = (lane >> 4) * 16;
    const int lbn = (lane & 7) + ((lane >> 4) & 1) * 8;
    const int lbk = ((lane >> 3) & 1) * 16;

    const __half* AU = (srcSel == 0) ? g_xh : (g_a1 + (size_t)u * SLAB);
    AU += (size_t)bm * HD;
    const __half* Wb = g_wh + (size_t)(layer * 8 + u) * 262144;
    __half* OH = (outSel ? g_h1 : g_h0) + (size_t)u * SLAB + (size_t)bm * HD + bn;

    ((float2*)sBias)[tid] = ((const float2*)(bias + u * HD))[tid];

    float acc[2][8][4];
    #pragma unroll
    for (int i = 0; i < 2; i++)
        #pragma unroll
        for (int j = 0; j < 8; j++)
            #pragma unroll
            for (int q = 0; q < 4; q++) acc[i][j][q] = 0.f;

    const int r0 = tid >> 2, q0 = tid & 3;

    auto issue = [&](int kt, int bufI) {
        uint32_t sbuf = sdyn + bufI * STG;
        const __half* Ap = AU + kt * 32;
        const __half* Bp = Wb + (size_t)kt * 16384 + (size_t)bn * 32;
        cpa16(sbuf + r0 * 80 + q0 * 16,            Ap + (size_t)r0 * HD + q0 * 8);
        cpa16(sbuf + (r0 + 64) * 80 + q0 * 16,     Ap + (size_t)(r0 + 64) * HD + q0 * 8);
        cpa16(sbuf + PLANE + r0 * 80 + q0 * 16,        Bp + r0 * 32 + q0 * 8);
        cpa16(sbuf + PLANE + (r0 + 64) * 80 + q0 * 16, Bp + (r0 + 64) * 32 + q0 * 8);
        CP_COMMIT();
    };

    issue(0, 0);

    #pragma unroll 1
    for (int kt = 0; kt < 16; ++kt) {
        const int s = kt & 1;
        if (kt < 15) {
            issue(kt + 1, 1 - s);
            asm volatile("cp.async.wait_group 1;" ::: "memory");
        } else {
            asm volatile("cp.async.wait_group 0;" ::: "memory");
        }
        __syncthreads();
        {
            const uint32_t aB = sdyn + s * STG;
            const uint32_t bB = aB + PLANE;
            #pragma unroll
            for (int k16 = 0; k16 < 2; k16++) {
                const int kb = k16 * 32;
                uint32_t a0[4], a1r[4];
                ldsm4(a0,  aB + (wm + la) * 80 + kb + lk);
                ldsm4(a1r, aB + (wm + 16 + la) * 80 + kb + lk);
                #pragma unroll
                for (int jp = 0; jp < 4; jp++) {
                    uint32_t b[4];
                    ldsm4(b, bB + (wn + 16 * jp + lbn) * 80 + kb + lbk);
                    #pragma unroll
                    for (int jj = 0; jj < 2; jj++) {
                        const int j = 2 * jp + jj;
                        mma16816(acc[0][j], a0,  b[2 * jj], b[2 * jj + 1]);
                        mma16816(acc[1][j], a1r, b[2 * jj], b[2 * jj + 1]);
                    }
                }
            }
        }
        __syncthreads();
    }

    // ---- epilogue: bias + relu -> fp16 ----
    #pragma unroll
    for (int i = 0; i < 2; i++) {
        #pragma unroll
        for (int j = 0; j < 8; j++) {
            int cb = wn + 8 * j + t4 * 2;
            float b0 = sBias[bn + cb], b1 = sBias[bn + cb + 1];
            float v0 = acc[i][j][0] + b0, v1 = acc[i][j][1] + b1;
            float v2 = acc[i][j][2] + b0, v3 = acc[i][j][3] + b1;
            v0 = v0 > 0.f ? v0 : 0.f; v1 = v1 > 0.f ? v1 : 0.f;
            v2 = v2 > 0.f ? v2 : 0.f; v3 = v3 > 0.f ? v3 : 0.f;
            int m0 = wm + 16 * i + g;
            *(uint32_t*)(OH + (size_t)m0 * HD + cb)       = pkh(v0, v1);
            *(uint32_t*)(OH + (size_t)(m0 + 8) * HD + cb) = pkh(v2, v3);
        }
    }
}

// ---------------- aggregation: a1[t] = sum_f c1n[t,f]*h0[f] (fp16 in/out) ------
__global__ void agg1_kernel() {
    __shared__ float c1s[64];
    int t = threadIdx.x;
    if (t < 64) c1s[t] = g_c1n[t];
    __syncthreads();
    size_t off = ((size_t)blockIdx.x * 256 + t) << 2;   // 4 halves per thread
    float2 h[8][2];
    #pragma unroll
    for (int f = 0; f < 8; f++) {
        uint2 p = *(const uint2*)(g_h0 + (size_t)f * SLAB + off);
        h[f][0] = __half22float2(*(const __half2*)&p.x);
        h[f][1] = __half22float2(*(const __half2*)&p.y);
    }
    #pragma unroll
    for (int u = 0; u < 8; u++) {
        float s0 = 0.f, s1 = 0.f, s2 = 0.f, s3 = 0.f;
        #pragma unroll
        for (int f = 0; f < 8; f++) {
            float c = c1s[u * 8 + f];
            s0 = fmaf(c, h[f][0].x, s0);
            s1 = fmaf(c, h[f][0].y, s1);
            s2 = fmaf(c, h[f][1].x, s2);
            s3 = fmaf(c, h[f][1].y, s3);
        }
        *(uint2*)(g_a1 + (size_t)u * SLAB + off) = make_uint2(pkh(s0, s1), pkh(s2, s3));
    }
}

// ============ fp16 output GEMM: out = sum_f h1[f] @ W2eff[f] + gbias ==========
// M=16384 (BM=64), N=64, K=4096 (8 f x 16 kt x 32). 8 warps 4x2, warp tile 16x32.
#define OPLANE 5120
#define OSTG   (2 * OPLANE)
#define OUT_SMEM (2 * OSTG)     // 20480

__global__ __launch_bounds__(256, 2)
void gemm_out_tc(float* __restrict__ Out) {
    extern __shared__ __align__(16) char dsm[];
    const uint32_t sdyn = smem_to_u32(dsm);
    const int tid = threadIdx.x;
    const int wid = tid >> 5, lane = tid & 31;
    const int g = lane >> 2, t4 = lane & 3;
    const int wm = (wid & 3) * 16;
    const int wn = (wid >> 2) * 32;
    const int bm = blockIdx.x * 64;

    const int la  = (lane & 7) + ((lane >> 3) & 1) * 8;
    const int lk  = (lane >> 4) * 16;
    const int lbn = (lane & 7) + ((lane >> 4) & 1) * 8;
    const int lbk = ((lane >> 3) & 1) * 16;

    float acc[4][4];
    #pragma unroll
    for (int j = 0; j < 4; j++)
        #pragma unroll
        for (int q = 0; q < 4; q++) acc[j][q] = 0.f;

    const int r0 = tid >> 2, q0 = tid & 3;   // 64 rows x 4 chunks

    auto issue = [&](int it, int bufI) {
        uint32_t sbuf = sdyn + bufI * OSTG;
        int f = it >> 4, kt = it & 15;
        const __half* Ap = g_h1 + (size_t)f * SLAB + (size_t)bm * HD + kt * 32;
        const __half* Bp = g_w2h + (size_t)(f * 16 + kt) * 2048;
        cpa16(sbuf + r0 * 80 + q0 * 16,          Ap + (size_t)r0 * HD + q0 * 8);
        cpa16(sbuf + OPLANE + r0 * 80 + q0 * 16, Bp + r0 * 32 + q0 * 8);
        CP_COMMIT();
    };

    issue(0, 0);

    #pragma unroll 1
    for (int it = 0; it < 128; ++it) {
        const int s = it & 1;
        if (it < 127) {
            issue(it + 1, 1 - s);
            asm volatile("cp.async.wait_group 1;" ::: "memory");
        } else {
            asm volatile("cp.async.wait_group 0;" ::: "memory");
        }
        __syncthreads();
        {
            const uint32_t aB = sdyn + s * OSTG;
            const uint32_t bB = aB + OPLANE;
            #pragma unroll
            for (int k16 = 0; k16 < 2; k16++) {
                const int kb = k16 * 32;
                uint32_t a[4];
                ldsm4(a, aB + (wm + la) * 80 + kb + lk);
                #pragma unroll
                for (int jp = 0; jp < 2; jp++) {
                    uint32_t b[4];
                    ldsm4(b, bB + (wn + 16 * jp + lbn) * 80 + kb + lbk);
                    mma16816(acc[2 * jp],     a, b[0], b[1]);
                    mma16816(acc[2 * jp + 1], a, b[2], b[3]);
                }
            }
        }
        __syncthreads();
    }

    // epilogue: + gbias, store (cols < NC)
    #pragma unroll
    for (int j = 0; j < 4; j++) {
        int c = wn + 8 * j + 2 * t4;
        float b0 = g_gbias[c], b1 = g_gbias[c + 1];
        int m0 = bm + wm + g;
        float v0 = acc[j][0] + b0, v1 = acc[j][1] + b1;
        float v2 = acc[j][2] + b0, v3 = acc[j][3] + b1;
        if (c < NC)     Out[(size_t)m0 * NC + c]           = v0;
        if (c + 1 < NC) Out[(size_t)m0 * NC + c + 1]       = v1;
        if (c < NC)     Out[(size_t)(m0 + 8) * NC + c]     = v2;
        if (c + 1 < NC) Out[(size_t)(m0 + 8) * NC + c + 1] = v3;
    }
}

// ---------------- launch ------------------------------------------------------
extern "C" void kernel_launch(void* const* d_in, const int* in_sizes, int n_in,
                              void* d_out, int out_size) {
    const float* x  = (const float*)d_in[0];
    const float* p1 = (const float*)d_in[1];
    const float* p2 = (const float*)d_in[2];
    const float* pf = (const float*)d_in[3];
    const float* W0 = (const float*)d_in[4];
    const float* b0 = (const float*)d_in[5];
    const float* W1 = (const float*)d_in[6];
    const float* b1 = (const float*)d_in[7];
    const float* W2 = (const float*)d_in[8];
    const float* b2 = (const float*)d_in[9];
    float* out = (float*)d_out;

    cudaFuncSetAttribute(gemm_fp16, cudaFuncAttributeMaxDynamicSharedMemorySize, GEMM_SMEM);
    cudaFuncSetAttribute(gemm_out_tc, cudaFuncAttributeMaxDynamicSharedMemorySize, OUT_SMEM);

    // fold policies + convert weights/inputs to fp16 layouts
    prep_small_kernel<<<1, 64>>>(p1, p2, pf, b2);
    prep_w2eff_kernel<<<1024, 256>>>(W2);
    conv_w_kernel<<<512, 256>>>(W0, W1);
    conv_x_kernel<<<8192, 256>>>(x);

    // stage A: h0[u] = relu(x @ W0[u] + b0[u]) -> g_h0 fp16
    gemm_fp16<<<dim3(128, 4, 8), 256, GEMM_SMEM>>>(0, 0, b0, 0);

    // aggregation: a1 = c1n-mix(h0) -> g_a1 fp16
    agg1_kernel<<<8192, 256>>>();

    // stage C: h1[u] = relu(a1[u] @ W1[u] + b1[u]) -> g_h1 fp16
    gemm_fp16<<<dim3(128, 4, 8), 256, GEMM_SMEM>>>(1, 1, b1, 1);

    // output: out = sum_f h1[f] @ W2eff[f] + gbias
    gemm_out_tc<<<256, 256, OUT_SMEM>>>(out);
}

// round 10
// speedup vs baseline: 5.2523x; 1.1611x over previous
#include <cuda_runtime.h>
#include <cuda_fp16.h>
#include <cstdint>

// Problem constants
#define BSZ 16384
#define HD  512
#define NC  62
#define UU  8
#define SLAB  ((size_t)BSZ * HD)   // per-unit plane elems (8M)

// ---------------- scratch (device globals; no allocation allowed) -------------
__device__ __align__(16) __half g_xh[(size_t)BSZ * HD];            // x fp16
__device__ __align__(16) __half g_h0[(size_t)UU * BSZ * HD];       // h0 fp16
__device__ __align__(16) __half g_a1[(size_t)UU * BSZ * HD];       // a1 fp16
__device__ __align__(16) __half g_h1[(size_t)UU * BSZ * HD];       // h1 fp16
__device__ __align__(16) __half g_wh[(size_t)2 * 8 * 8 * 512 * 64];  // [(l*8+u)][k8][n512][k64]
__device__ __align__(16) __half g_w2h[(size_t)8 * 8 * 64 * 64];      // [(f*8+k8)][n64][k64]
__device__ float g_c1n[64];
__device__ float g_c2g[64];
__device__ float g_gbias[64];

// ---------------- helpers -----------------------------------------------------
__device__ __forceinline__ uint32_t smem_to_u32(const void* p) {
    uint32_t a;
    asm("{ .reg .u64 t; cvta.to.shared.u64 t, %1; cvt.u32.u64 %0, t; }" : "=r"(a) : "l"(p));
    return a;
}
__device__ __forceinline__ void ldsm4(uint32_t* r, uint32_t addr) {
    asm volatile("ldmatrix.sync.aligned.m8n8.x4.shared.b16 {%0,%1,%2,%3}, [%4];"
        : "=r"(r[0]), "=r"(r[1]), "=r"(r[2]), "=r"(r[3]) : "r"(addr));
}
__device__ __forceinline__ void mma16816(float* c, const uint32_t* a,
                                         uint32_t b0, uint32_t b1) {
    asm volatile(
        "mma.sync.aligned.m16n8k16.row.col.f32.f16.f16.f32 "
        "{%0,%1,%2,%3}, {%4,%5,%6,%7}, {%8,%9}, {%0,%1,%2,%3};"
        : "+f"(c[0]), "+f"(c[1]), "+f"(c[2]), "+f"(c[3])
        : "r"(a[0]), "r"(a[1]), "r"(a[2]), "r"(a[3]), "r"(b0), "r"(b1));
}
__device__ __forceinline__ void cpa16(uint32_t d, const void* s) {
    asm volatile("cp.async.cg.shared.global [%0], [%1], 16;" :: "r"(d), "l"(s));
}
#define CP_COMMIT() asm volatile("cp.async.commit_group;" ::: "memory")

__device__ __forceinline__ uint32_t pkh(float a, float b) {
    __half ha = __float2half(a), hb = __float2half(b);
    return (uint32_t)__half_as_ushort(ha) | ((uint32_t)__half_as_ushort(hb) << 16);
}

// ---------------- prep: tiny policy/bias folding ------------------------------
__global__ void prep_small_kernel(const float* __restrict__ p1,
                                  const float* __restrict__ p2,
                                  const float* __restrict__ pf,
                                  const float* __restrict__ b2) {
    __shared__ float gs[8];
    int t = threadIdx.x;
    if (t == 0) {
        float d = 0.f;
        for (int j = 0; j < 8; j++) d += pf[j];
        float inv = d > 0.f ? 1.f / d : 1.f;
        float acc = 1.f;
        for (int j = 7; j >= 0; --j) { acc *= inv; gs[j] = pf[j] * acc; }
    }
    __syncthreads();
    if (t < 8) {
        float r1 = 0.f, r2 = 0.f;
        for (int f = 0; f < 8; f++) { r1 += p1[t * 8 + f]; r2 += p2[t * 8 + f]; }
        float i1 = r1 > 0.f ? 1.f / r1 : 1.f;
        float i2 = r2 > 0.f ? 1.f / r2 : 1.f;
        for (int f = 0; f < 8; f++) {
            g_c1n[t * 8 + f] = p1[t * 8 + f] * i1;
            g_c2g[t * 8 + f] = gs[t] * p2[t * 8 + f] * i2;
        }
    }
    if (t < 62) {
        float s = 0.f;
        for (int j = 0; j < 8; j++) s += gs[j] * b2[j * NC + t];
        g_gbias[t] = s;
    } else if (t < 64) {
        g_gbias[t] = 0.f;
    }
}

// W2eff -> fp16, layout [(f*8+k8)][n64][k64]
__global__ void prep_w2eff_kernel(const float* __restrict__ W2) {
    int idx = blockIdx.x * 256 + threadIdx.x;    // 262144
    int f = idx >> 15;
    int k512 = (idx >> 6) & 511;
    int n = idx & 63;
    float s = 0.f;
    if (n < NC) {
        #pragma unroll
        for (int j = 0; j < 8; j++)
            s = fmaf(g_c2g[j * 8 + f], W2[((size_t)(j * 512) + k512) * NC + n], s);
    }
    int k8 = k512 >> 6, kk = k512 & 63;
    g_w2h[((size_t)(f * 8 + k8) * 64 + n) * 64 + kk] = __float2half(s);
}

// W0, W1 transpose -> fp16, layout [(l*8+u)][k8][n512][k64]
__global__ void conv_w_kernel(const float* __restrict__ W0, const float* __restrict__ W1) {
    int idx = blockIdx.x * 256 + threadIdx.x;   // 65536 total
    int n  = idx & 511;
    int r  = idx >> 9;          // (l*8+u)*8 + k8, < 128
    int k8 = r & 7;
    int ug = r >> 3;
    const float* W = (ug >= 8 ? W1 : W0) + ((size_t)(ug & 7) << 18);
    unsigned short hv[64];
    #pragma unroll 8
    for (int i = 0; i < 64; i++)
        hv[i] = __half_as_ushort(__float2half(W[(size_t)(k8 * 64 + i) * 512 + n]));
    __half* dst = g_wh + ((size_t)r * 512 + n) * 64;
    #pragma unroll
    for (int i = 0; i < 8; i++)
        *(uint4*)(dst + i * 8) = *(uint4*)(hv + i * 8);
}

// x -> fp16
__global__ void conv_x_kernel(const float* __restrict__ x) {
    size_t off = ((size_t)blockIdx.x * 256 + threadIdx.x) << 2;
    float4 v = *(const float4*)(x + off);
    *(uint2*)(g_xh + off) = make_uint2(pkh(v.x, v.y), pkh(v.z, v.w));
}

// ============= fp16 HMMA GEMM: C[u] = relu(A[u] @ W[u] + b[u]) ================
// M=16384, N=512, K=512. BM=128, BN=128, BK=64. 8 warps 4x2, warp tile 32x64.
// SMEM rows: 64 halves + 8 pad = 144 B (ldsm bank-conflict-free, cp.async 16B).
#define ROWB  144
#define PLANE (128 * ROWB)          // 18432
#define STG   (2 * PLANE)
#define GEMM_SMEM (2 * STG)         // 73728

__global__ __launch_bounds__(256, 2)
void gemm_fp16(int srcSel, int layer, const float* __restrict__ bias, int outSel) {
    extern __shared__ __align__(16) char dsm[];
    __shared__ float sBias[512];
    const uint32_t sdyn = smem_to_u32(dsm);

    const int tid = threadIdx.x;
    const int wid = tid >> 5, lane = tid & 31;
    const int g = lane >> 2, t4 = lane & 3;
    const int wm = (wid >> 1) * 32;
    const int wn = (wid & 1) * 64;
    const int u  = blockIdx.z;
    const int bm = blockIdx.x * 128;
    const int bn = blockIdx.y * 128;

    // ldmatrix lane decodes (validated R5-R8)
    const int la  = (lane & 7) + ((lane >> 3) & 1) * 8;
    const int lk  = (lane >> 4) * 16;
    const int lbn = (lane & 7) + ((lane >> 4) & 1) * 8;
    const int lbk = ((lane >> 3) & 1) * 16;

    const __half* AU = (srcSel == 0) ? g_xh : (g_a1 + (size_t)u * SLAB);
    AU += (size_t)bm * HD;
    const __half* Wb = g_wh + (size_t)(layer * 8 + u) * 262144;
    __half* OH = (outSel ? g_h1 : g_h0) + (size_t)u * SLAB + (size_t)bm * HD + bn;

    ((float2*)sBias)[tid] = ((const float2*)(bias + u * HD))[tid];

    float acc[2][8][4];
    #pragma unroll
    for (int i = 0; i < 2; i++)
        #pragma unroll
        for (int j = 0; j < 8; j++)
            #pragma unroll
            for (int q = 0; q < 4; q++) acc[i][j][q] = 0.f;

    // staging: 1024 16B-chunks per plane; thread handles 4 A + 4 B
    const int r0 = tid >> 3, q0 = tid & 7;   // row step 32 per i

    auto issue = [&](int kt, int bufI) {
        uint32_t sbuf = sdyn + bufI * STG;
        const __half* Ap = AU + kt * 64;
        const __half* Bp = Wb + (size_t)kt * 32768 + (size_t)bn * 64;
        #pragma unroll
        for (int i = 0; i < 4; i++) {
            int row = r0 + i * 32;
            cpa16(sbuf + row * ROWB + q0 * 16,         Ap + (size_t)row * HD + q0 * 8);
            cpa16(sbuf + PLANE + row * ROWB + q0 * 16, Bp + (size_t)row * 64 + q0 * 8);
        }
        CP_COMMIT();
    };

    issue(0, 0);

    #pragma unroll 1
    for (int kt = 0; kt < 8; ++kt) {
        const int s = kt & 1;
        if (kt < 7) {
            issue(kt + 1, 1 - s);
            asm volatile("cp.async.wait_group 1;" ::: "memory");
        } else {
            asm volatile("cp.async.wait_group 0;" ::: "memory");
        }
        __syncthreads();
        {
            const uint32_t aB = sdyn + s * STG;
            const uint32_t bB = aB + PLANE;
            #pragma unroll
            for (int k16 = 0; k16 < 4; k16++) {
                const int kb = k16 * 32;
                uint32_t a0[4], a1r[4];
                ldsm4(a0,  aB + (wm + la) * ROWB + kb + lk);
                ldsm4(a1r, aB + (wm + 16 + la) * ROWB + kb + lk);
                #pragma unroll
                for (int jp = 0; jp < 4; jp++) {
                    uint32_t b[4];
                    ldsm4(b, bB + (wn + 16 * jp + lbn) * ROWB + kb + lbk);
                    #pragma unroll
                    for (int jj = 0; jj < 2; jj++) {
                        const int j = 2 * jp + jj;
                        mma16816(acc[0][j], a0,  b[2 * jj], b[2 * jj + 1]);
                        mma16816(acc[1][j], a1r, b[2 * jj], b[2 * jj + 1]);
                    }
                }
            }
        }
        __syncthreads();
    }

    // ---- epilogue: bias + relu -> fp16 ----
    #pragma unroll
    for (int i = 0; i < 2; i++) {
        #pragma unroll
        for (int j = 0; j < 8; j++) {
            int cb = wn + 8 * j + t4 * 2;
            float b0 = sBias[bn + cb], b1 = sBias[bn + cb + 1];
            float v0 = acc[i][j][0] + b0, v1 = acc[i][j][1] + b1;
            float v2 = acc[i][j][2] + b0, v3 = acc[i][j][3] + b1;
            v0 = v0 > 0.f ? v0 : 0.f; v1 = v1 > 0.f ? v1 : 0.f;
            v2 = v2 > 0.f ? v2 : 0.f; v3 = v3 > 0.f ? v3 : 0.f;
            int m0 = wm + 16 * i + g;
            *(uint32_t*)(OH + (size_t)m0 * HD + cb)       = pkh(v0, v1);
            *(uint32_t*)(OH + (size_t)(m0 + 8) * HD + cb) = pkh(v2, v3);
        }
    }
}

// ---------------- aggregation: a1[t] = sum_f c1n[t,f]*h0[f] (fp16 in/out) ------
__global__ void agg1_kernel() {
    __shared__ float c1s[64];
    int t = threadIdx.x;
    if (t < 64) c1s[t] = g_c1n[t];
    __syncthreads();
    size_t off = ((size_t)blockIdx.x * 256 + t) << 2;   // 4 halves per thread
    float2 h[8][2];
    #pragma unroll
    for (int f = 0; f < 8; f++) {
        uint2 p = *(const uint2*)(g_h0 + (size_t)f * SLAB + off);
        h[f][0] = __half22float2(*(const __half2*)&p.x);
        h[f][1] = __half22float2(*(const __half2*)&p.y);
    }
    #pragma unroll
    for (int u = 0; u < 8; u++) {
        float s0 = 0.f, s1 = 0.f, s2 = 0.f, s3 = 0.f;
        #pragma unroll
        for (int f = 0; f < 8; f++) {
            float c = c1s[u * 8 + f];
            s0 = fmaf(c, h[f][0].x, s0);
            s1 = fmaf(c, h[f][0].y, s1);
            s2 = fmaf(c, h[f][1].x, s2);
            s3 = fmaf(c, h[f][1].y, s3);
        }
        *(uint2*)(g_a1 + (size_t)u * SLAB + off) = make_uint2(pkh(s0, s1), pkh(s2, s3));
    }
}

// ============ fp16 output GEMM: out = sum_f h1[f] @ W2eff[f] + gbias ==========
// M=16384 (BM=64), N=64, K=4096 (8 f x 8 k8 x 64). 8 warps 4x2, warp tile 16x32.
#define OPLANE (64 * ROWB)          // 9216
#define OSTG   (2 * OPLANE)
#define OUT_SMEM (2 * OSTG)         // 36864

__global__ __launch_bounds__(256, 2)
void gemm_out_tc(float* __restrict__ Out) {
    extern __shared__ __align__(16) char dsm[];
    const uint32_t sdyn = smem_to_u32(dsm);
    const int tid = threadIdx.x;
    const int wid = tid >> 5, lane = tid & 31;
    const int g = lane >> 2, t4 = lane & 3;
    const int wm = (wid & 3) * 16;
    const int wn = (wid >> 2) * 32;
    const int bm = blockIdx.x * 64;

    const int la  = (lane & 7) + ((lane >> 3) & 1) * 8;
    const int lk  = (lane >> 4) * 16;
    const int lbn = (lane & 7) + ((lane >> 4) & 1) * 8;
    const int lbk = ((lane >> 3) & 1) * 16;

    float acc[4][4];
    #pragma unroll
    for (int j = 0; j < 4; j++)
        #pragma unroll
        for (int q = 0; q < 4; q++) acc[j][q] = 0.f;

    const int r0 = tid >> 3, q0 = tid & 7;   // 32 rows per i-step

    auto issue = [&](int it, int bufI) {
        uint32_t sbuf = sdyn + bufI * OSTG;
        int f = it >> 3, k8 = it & 7;
        const __half* Ap = g_h1 + (size_t)f * SLAB + (size_t)bm * HD + k8 * 64;
        const __half* Bp = g_w2h + (size_t)(f * 8 + k8) * 4096;
        #pragma unroll
        for (int i = 0; i < 2; i++) {
            int row = r0 + i * 32;
            cpa16(sbuf + row * ROWB + q0 * 16, Ap + (size_t)row * HD + q0 * 8);
            cpa16(sbuf + OPLANE + row * ROWB + q0 * 16, Bp + (size_t)row * 64 + q0 * 8);
        }
        CP_COMMIT();
    };

    issue(0, 0);

    #pragma unroll 1
    for (int it = 0; it < 64; ++it) {
        const int s = it & 1;
        if (it < 63) {
            issue(it + 1, 1 - s);
            asm volatile("cp.async.wait_group 1;" ::: "memory");
        } else {
            asm volatile("cp.async.wait_group 0;" ::: "memory");
        }
        __syncthreads();
        {
            const uint32_t aB = sdyn + s * OSTG;
            const uint32_t bB = aB + OPLANE;
            #pragma unroll
            for (int k16 = 0; k16 < 4; k16++) {
                const int kb = k16 * 32;
                uint32_t a[4];
                ldsm4(a, aB + (wm + la) * ROWB + kb + lk);
                #pragma unroll
                for (int jp = 0; jp < 2; jp++) {
                    uint32_t b[4];
                    ldsm4(b, bB + (wn + 16 * jp + lbn) * ROWB + kb + lbk);
                    mma16816(acc[2 * jp],     a, b[0], b[1]);
                    mma16816(acc[2 * jp + 1], a, b[2], b[3]);
                }
            }
        }
        __syncthreads();
    }

    // epilogue: + gbias, store (cols < NC)
    #pragma unroll
    for (int j = 0; j < 4; j++) {
        int c = wn + 8 * j + 2 * t4;
        float b0 = g_gbias[c], b1 = g_gbias[c + 1];
        int m0 = bm + wm + g;
        float v0 = acc[j][0] + b0, v1 = acc[j][1] + b1;
        float v2 = acc[j][2] + b0, v3 = acc[j][3] + b1;
        if (c < NC)     Out[(size_t)m0 * NC + c]           = v0;
        if (c + 1 < NC) Out[(size_t)m0 * NC + c + 1]       = v1;
        if (c < NC)     Out[(size_t)(m0 + 8) * NC + c]     = v2;
        if (c + 1 < NC) Out[(size_t)(m0 + 8) * NC + c + 1] = v3;
    }
}

// ---------------- launch ------------------------------------------------------
extern "C" void kernel_launch(void* const* d_in, const int* in_sizes, int n_in,
                              void* d_out, int out_size) {
    const float* x  = (const float*)d_in[0];
    const float* p1 = (const float*)d_in[1];
    const float* p2 = (const float*)d_in[2];
    const float* pf = (const float*)d_in[3];
    const float* W0 = (const float*)d_in[4];
    const float* b0 = (const float*)d_in[5];
    const float* W1 = (const float*)d_in[6];
    const float* b1 = (const float*)d_in[7];
    const float* W2 = (const float*)d_in[8];
    const float* b2 = (const float*)d_in[9];
    float* out = (float*)d_out;

    cudaFuncSetAttribute(gemm_fp16, cudaFuncAttributeMaxDynamicSharedMemorySize, GEMM_SMEM);
    cudaFuncSetAttribute(gemm_out_tc, cudaFuncAttributeMaxDynamicSharedMemorySize, OUT_SMEM);

    // fold policies + convert weights/inputs to fp16 k64 layouts
    prep_small_kernel<<<1, 64>>>(p1, p2, pf, b2);
    prep_w2eff_kernel<<<1024, 256>>>(W2);
    conv_w_kernel<<<256, 256>>>(W0, W1);
    conv_x_kernel<<<8192, 256>>>(x);

    // stage A: h0[u] = relu(x @ W0[u] + b0[u]) -> g_h0 fp16
    gemm_fp16<<<dim3(128, 4, 8), 256, GEMM_SMEM>>>(0, 0, b0, 0);

    // aggregation: a1 = c1n-mix(h0) -> g_a1 fp16
    agg1_kernel<<<8192, 256>>>();

    // stage C: h1[u] = relu(a1[u] @ W1[u] + b1[u]) -> g_h1 fp16
    gemm_fp16<<<dim3(128, 4, 8), 256, GEMM_SMEM>>>(1, 1, b1, 1);

    // output: out = sum_f h1[f] @ W2eff[f] + gbias
    gemm_out_tc<<<256, 256, OUT_SMEM>>>(out);
}